// round 1
// baseline (speedup 1.0000x reference)
#include <cuda_runtime.h>
#include <cuda_bf16.h>

#define NT   1000
#define NS   2048
#define NH   16
#define NR   8
#define HS   256
#define NG   32
#define NO   48
#define TOUT (NT - NR + 1)   // 993
#define TILE_T 32
#define WT_STRIDE 260        // 48 rows x 260 floats; 1040B row stride (16B aligned)

// ---------------- device scratch (static, no allocations) ----------------
__device__ float g_zbase[NS*HS];      // state + b_kin
__device__ float g_hg[NS*HS];         // tanh(state)
__device__ float g_prm[9][NS*NH];     // 0 kp,1 ks,2 kd,3 gd,4 gl,5 qb,6 gi,7 ge,8 ga
__device__ float g_wr[NS*NH*NR];
__device__ float g_km[NT*NS*NH];
__device__ float g_ki[NT*NS*NH];
__device__ float g_ke[NT*NS*NH];
__device__ float g_Ps[NT*NS];
__device__ float g_Pl[NT*NS];
__device__ float g_Ev[NT*NS];

__device__ __forceinline__ float tanh_fast(float x) {
    float y;
    asm("tanh.approx.f32 %0, %1;" : "=f"(y) : "f"(x));
    return y;
}
__device__ __forceinline__ float sigf(float v) { return 1.f / (1.f + expf(-v)); }

// ---------------- kernel 1: state = xc@W_fc + b_fc ----------------
__global__ void k_state(const float* __restrict__ xc, const float* __restrict__ W_fc,
                        const float* __restrict__ b_fc, const float* __restrict__ b_kin) {
    int s = blockIdx.x, j = threadIdx.x;
    __shared__ float xcs[NG];
    if (j < NG) xcs[j] = xc[s*NG + j];
    __syncthreads();
    float acc = b_fc[j];
#pragma unroll
    for (int g = 0; g < NG; g++) acc = fmaf(xcs[g], W_fc[g*HS + j], acc);
    g_zbase[s*HS + j] = acc + b_kin[j];
    g_hg[s*HS + j]    = tanhf(acc);
}

// ---------------- kernel 2: per-site gate params + routing weights ----------------
__global__ void k_params(const float* __restrict__ W_r, const float* __restrict__ b_r,
                         const float* __restrict__ W_g, const float* __restrict__ b_g) {
    int s = blockIdx.x, tid = threadIdx.x;
    __shared__ float hgs[HS];
    __shared__ float pG[144], pR[144];
    hgs[tid] = g_hg[s*HS + tid];
    __syncthreads();
    for (int idx = tid; idx < 288; idx += 256) {
        int o = (idx < 144) ? idx : idx - 144;
        const float* W = (idx < 144) ? W_g : W_r;
        float acc = (idx < 144) ? b_g[o] : b_r[o];
#pragma unroll 8
        for (int k = 0; k < HS; k++) acc = fmaf(hgs[k], W[k*144 + o], acc);
        if (idx < 144) pG[o] = acc; else pR[o] = acc;
    }
    __syncthreads();
    if (tid < NH) {
        int h = tid, gid = s*NH + h;
        float g0 = pG[0*16+h], g1 = pG[1*16+h], g2 = pG[2*16+h], g3 = pG[3*16+h];
        float g4 = pG[4*16+h], g5 = pG[5*16+h], g7 = pG[7*16+h], g8 = pG[8*16+h];
        g_prm[0][gid] = sigf(g0);
        g_prm[1][gid] = sigf(g1);
        g_prm[2][gid] = sigf(g2);
        g_prm[3][gid] = sigf(g3);
        float t = sigf(g4) * 10.f; g_prm[4][gid] = t*t*t;
        g_prm[5][gid] = fmaxf(g5, 0.f) * 0.1f;
        g_prm[6][gid] = fminf(fmaxf(g7*(1.f/6.f) + 0.5f, 0.f), 1.f) * 0.5f;
        g_prm[7][gid] = fmaxf(g8, 0.f);
        // ga = softmax over heads of g(6)
        float m = -1e30f;
#pragma unroll
        for (int i = 0; i < 16; i++) m = fmaxf(m, pG[6*16+i]);
        float sum = 0.f;
#pragma unroll
        for (int i = 0; i < 16; i++) sum += expf(pG[6*16+i] - m);
        g_prm[8][gid] = expf(pG[6*16+h] - m) / sum;
        // wr: softmax over 9, cumsum, fold, normalize first 8
        float r[9];
        float rm = -1e30f;
#pragma unroll
        for (int i = 0; i < 9; i++) { r[i] = pR[h*9 + i]; rm = fmaxf(rm, r[i]); }
        float rs = 0.f;
#pragma unroll
        for (int i = 0; i < 9; i++) { r[i] = expf(r[i] - rm); rs += r[i]; }
        float inv = 1.f / rs;
        float c = 0.f, w[8], ws = 0.f;
#pragma unroll
        for (int i = 0; i < 8; i++) {
            float si = r[i] * inv;
            c += si;
            float wi = fminf(c, 1.f - c + si);
            w[i] = wi; ws += wi;
        }
        float wsi = 1.f / ws;
#pragma unroll
        for (int i = 0; i < 8; i++) g_wr[gid*NR + i] = w[i] * wsi;
    }
}

// ---------------- kernel 3: big K-param MLP (block per site) ----------------
__device__ __forceinline__ void stor_k(int base, int o, float v) {
    int h = o & 15;
    if (o < 16)       g_km[base + h] = __expf(v);
    else if (o < 32)  g_ki[base + h] = fmaxf(v, 0.f);
    else              g_ke[base + h] = __expf(v);
}

__global__ void __launch_bounds__(256, 2) k_kparam(
        const float* __restrict__ x, const float* __restrict__ W_kin,
        const float* __restrict__ W_kout, const float* __restrict__ b_kout) {
    extern __shared__ float sm[];
    float* hsh = sm;                      // TILE_T * HS
    float* wt  = sm + TILE_T*HS;          // 48 * WT_STRIDE (transposed W_kout)
    float* ft  = wt + NO*WT_STRIDE;       // TILE_T * 4
    int s = blockIdx.x, tid = threadIdx.x;

    // transpose W_kout into shared: wt[o][k]
    for (int idx = tid; idx < HS*NO; idx += 256) {
        int k = idx / NO, o = idx - k*NO;
        wt[o*WT_STRIDE + k] = W_kout[idx];
    }
    float zb  = g_zbase[s*HS + tid];
    float wk0 = W_kin[0*HS + tid], wk1 = W_kin[1*HS + tid];
    float wk2 = W_kin[2*HS + tid], wk3 = W_kin[3*HS + tid];

    int og = tid & 15, tg = tid >> 4;
    int ob = og * 3;
    float bo0 = b_kout[ob], bo1 = b_kout[ob+1], bo2 = b_kout[ob+2];
    const float4* w0 = (const float4*)(wt + (ob+0)*WT_STRIDE);
    const float4* w1 = (const float4*)(wt + (ob+1)*WT_STRIDE);
    const float4* w2 = (const float4*)(wt + (ob+2)*WT_STRIDE);
    const float4* hv0 = (const float4*)(hsh + tg*HS);
    const float4* hv1 = (const float4*)(hsh + (tg+16)*HS);

    for (int tb = 0; tb < NT; tb += TILE_T) {
        __syncthreads();   // previous tile's phase-2 reads done
        if (tid < TILE_T) {
            int t = tb + tid;
            if (t < NT) {
                const float* xr = x + (size_t)(t*NS + s) * 6;
                float Prcp = xr[0], Evp = xr[1], T1 = xr[2], T2 = xr[3];
                ft[tid*4+0] = T1; ft[tid*4+1] = T2;
                ft[tid*4+2] = xr[4]; ft[tid*4+3] = xr[5];
                float fl = fminf(fmaxf(T2 / (T2 - T1 + 1e-5f), 0.f), 1.f);
                g_Pl[t*NS + s] = Prcp * fl;
                g_Ps[t*NS + s] = Prcp * (1.f - fl);
                g_Ev[t*NS + s] = Evp;
            } else {
                ft[tid*4+0] = 0.f; ft[tid*4+1] = 0.f;
                ft[tid*4+2] = 0.f; ft[tid*4+3] = 0.f;
            }
        }
        __syncthreads();
        // phase 1: hidden tile, thread = hidden unit
#pragma unroll
        for (int tt = 0; tt < TILE_T; tt++) {
            float z = zb;
            z = fmaf(ft[tt*4+0], wk0, z);
            z = fmaf(ft[tt*4+1], wk1, z);
            z = fmaf(ft[tt*4+2], wk2, z);
            z = fmaf(ft[tt*4+3], wk3, z);
            hsh[tt*HS + tid] = tanh_fast(z);
        }
        __syncthreads();
        // phase 2: 48-wide projection, thread tile = 2 timesteps x 3 outputs
        float a00=0.f,a01=0.f,a02=0.f,a10=0.f,a11=0.f,a12=0.f;
#pragma unroll 8
        for (int k4 = 0; k4 < HS/4; k4++) {
            float4 ha = hv0[k4], hb = hv1[k4];
            float4 p = w0[k4], q = w1[k4], r = w2[k4];
            a00 = fmaf(ha.x,p.x, fmaf(ha.y,p.y, fmaf(ha.z,p.z, fmaf(ha.w,p.w, a00))));
            a01 = fmaf(ha.x,q.x, fmaf(ha.y,q.y, fmaf(ha.z,q.z, fmaf(ha.w,q.w, a01))));
            a02 = fmaf(ha.x,r.x, fmaf(ha.y,r.y, fmaf(ha.z,r.z, fmaf(ha.w,r.w, a02))));
            a10 = fmaf(hb.x,p.x, fmaf(hb.y,p.y, fmaf(hb.z,p.z, fmaf(hb.w,p.w, a10))));
            a11 = fmaf(hb.x,q.x, fmaf(hb.y,q.y, fmaf(hb.z,q.z, fmaf(hb.w,q.w, a11))));
            a12 = fmaf(hb.x,r.x, fmaf(hb.y,r.y, fmaf(hb.z,r.z, fmaf(hb.w,r.w, a12))));
        }
        int t0g = tb + tg, t1g = tb + tg + 16;
        if (t0g < NT) {
            int base = t0g*NS*NH + s*NH;
            stor_k(base, ob+0, a00+bo0);
            stor_k(base, ob+1, a01+bo1);
            stor_k(base, ob+2, a02+bo2);
        }
        if (t1g < NT) {
            int base = t1g*NS*NH + s*NH;
            stor_k(base, ob+0, a10+bo0);
            stor_k(base, ob+1, a11+bo1);
            stor_k(base, ob+2, a12+bo2);
        }
    }
}

// ---------------- kernel 4: fused scan + routing conv + head reduction ----------------
__global__ void k_scan(float* __restrict__ out) {
    int gid = blockIdx.x * blockDim.x + threadIdx.x;   // = s*NH + h
    int site = gid >> 4, h = gid & 15;
    float kp = g_prm[0][gid], ksg = g_prm[1][gid], kd = g_prm[2][gid];
    float gd = g_prm[3][gid], gl = g_prm[4][gid], qb = g_prm[5][gid];
    float gi = g_prm[6][gid], ge = g_prm[7][gid], ga = g_prm[8][gid];
    const float4* wrp = (const float4*)(g_wr + gid*NR);
    float4 wa = wrp[0], wb = wrp[1];
    float wrv[8] = {wa.x, wa.y, wa.z, wa.w, wb.x, wb.y, wb.z, wb.w};

    float A[8];
#pragma unroll
    for (int j = 0; j < 8; j++) A[j] = 0.f;
    float Sf = 0.f, Ss = 0.f, Sg = 0.f;

    const float* pkm = g_km + gid;
    const float* pki = g_ki + gid;
    const float* pke = g_ke + gid;

    for (int t = 0; t < NT; t++) {
        float Pst = g_Ps[t*NS + site];
        float Plt = g_Pl[t*NS + site];
        float Evt = g_Ev[t*NS + site];
        int off = t * (NS*NH);
        float kmt = pkm[off], kit = pki[off], ket = pke[off];

        Sf += Pst;
        float qf = fminf(Sf, kmt); Sf -= qf;
        float inflow = qf + Plt;
        float qd = inflow * gi;
        Ss += inflow * (1.f - gi);
        float E = fminf(fmaxf(Ss, 0.f), Evt * ket * ge); Ss -= E;
        float qi = fminf(kit, fmaxf(Ss, 0.f)); Ss -= qi;
        float qp = kp * fmaxf(Ss - gl, 0.f);
        float qsa = ksg * fminf(fmaxf(Ss, 0.f), gl);
        Ss -= qp + qsa;
        Sg += qsa * gd;
        float qg = fmaf(kd, Sg, qb); Sg *= (1.f - kd);
        float q = qp + qsa * (1.f - gd) + qg + qd + qi;

#pragma unroll
        for (int j = 0; j < 8; j++) A[j] = fmaf(q, wrv[j], A[j]);

        if (t >= NR - 1) {
            float v = A[0] * ga;
            v += __shfl_xor_sync(0xffffffffu, v, 1);
            v += __shfl_xor_sync(0xffffffffu, v, 2);
            v += __shfl_xor_sync(0xffffffffu, v, 4);
            v += __shfl_xor_sync(0xffffffffu, v, 8);
            if (h == 0) out[(t - (NR-1))*NS + site] = v;
        }
#pragma unroll
        for (int j = 0; j < 7; j++) A[j] = A[j+1];
        A[7] = 0.f;
    }
}

// ---------------- launch ----------------
extern "C" void kernel_launch(void* const* d_in, const int* in_sizes, int n_in,
                              void* d_out, int out_size) {
    const float* x      = (const float*)d_in[0];
    const float* xc     = (const float*)d_in[1];
    const float* W_fc   = (const float*)d_in[2];
    const float* b_fc   = (const float*)d_in[3];
    const float* W_r    = (const float*)d_in[4];
    const float* b_r    = (const float*)d_in[5];
    const float* W_g    = (const float*)d_in[6];
    const float* b_g    = (const float*)d_in[7];
    const float* W_kin  = (const float*)d_in[8];
    const float* b_kin  = (const float*)d_in[9];
    const float* W_kout = (const float*)d_in[10];
    const float* b_kout = (const float*)d_in[11];
    float* out = (float*)d_out;

    k_state<<<NS, HS>>>(xc, W_fc, b_fc, b_kin);
    k_params<<<NS, 256>>>(W_r, b_r, W_g, b_g);

    size_t smem = (size_t)(TILE_T*HS + NO*WT_STRIDE + TILE_T*4) * sizeof(float); // 83200 B
    cudaFuncSetAttribute(k_kparam, cudaFuncAttributeMaxDynamicSharedMemorySize, (int)smem);
    k_kparam<<<NS, 256, smem>>>(x, W_kin, W_kout, b_kout);

    k_scan<<<(NS*NH)/128, 128>>>(out);
}

// round 2
// speedup vs baseline: 1.3296x; 1.3296x over previous
#include <cuda_runtime.h>
#include <cuda_bf16.h>

#define NT   1000
#define NS   2048
#define NH   16
#define NR   8
#define HS   256
#define NG   32
#define NO   48
#define NSNH (NS*NH)
#define TOUT (NT - NR + 1)   // 993
#define TILE_T 128
#define HROW 260             // padded row stride (floats); 1040B, 16B aligned, +4 bank skew

// ---------------- device scratch (static, no allocations) ----------------
__device__ float g_zbase[NS*HS];      // state + b_kin
__device__ float g_hg[NS*HS];         // tanh(state)
__device__ float g_prm[9][NS*NH];     // 0 kp,1 ks,2 kd,3 gd,4 gl,5 qb,6 gi,7 ge,8 ga
__device__ float g_wr[NS*NH*NR];
__device__ float g_km[NT*NS*NH];
__device__ float g_ki[NT*NS*NH];
__device__ float g_ke[NT*NS*NH];
__device__ float g_Ps[NT*NS];
__device__ float g_Pl[NT*NS];
__device__ float g_Ev[NT*NS];

__device__ __forceinline__ float tanh_fast(float x) {
    float y;
    asm("tanh.approx.f32 %0, %1;" : "=f"(y) : "f"(x));
    return y;
}
__device__ __forceinline__ float sigf(float v) { return 1.f / (1.f + expf(-v)); }

// packed f32x2 FMA (FFMA2) — PTX-only pattern on sm_103a
#define FFMA2(d, a, b) asm("fma.rn.f32x2 %0, %1, %2, %0;" : "+l"(d) : "l"(a), "l"(b))

__device__ __forceinline__ float psum(unsigned long long u) {
    float lo, hi;
    asm("mov.b64 {%0,%1}, %2;" : "=f"(lo), "=f"(hi) : "l"(u));
    return lo + hi;
}

// ---------------- kernel 1: state = xc@W_fc + b_fc ----------------
__global__ void k_state(const float* __restrict__ xc, const float* __restrict__ W_fc,
                        const float* __restrict__ b_fc, const float* __restrict__ b_kin) {
    int s = blockIdx.x, j = threadIdx.x;
    __shared__ float xcs[NG];
    if (j < NG) xcs[j] = xc[s*NG + j];
    __syncthreads();
    float acc = b_fc[j];
#pragma unroll
    for (int g = 0; g < NG; g++) acc = fmaf(xcs[g], W_fc[g*HS + j], acc);
    g_zbase[s*HS + j] = acc + b_kin[j];
    g_hg[s*HS + j]    = tanhf(acc);
}

// ---------------- kernel 2: per-site gate params + routing weights ----------------
__global__ void k_params(const float* __restrict__ W_r, const float* __restrict__ b_r,
                         const float* __restrict__ W_g, const float* __restrict__ b_g) {
    int s = blockIdx.x, tid = threadIdx.x;
    __shared__ float hgs[HS];
    __shared__ float pG[144], pR[144];
    hgs[tid] = g_hg[s*HS + tid];
    __syncthreads();
    for (int idx = tid; idx < 288; idx += 256) {
        int o = (idx < 144) ? idx : idx - 144;
        const float* W = (idx < 144) ? W_g : W_r;
        float acc = (idx < 144) ? b_g[o] : b_r[o];
#pragma unroll 8
        for (int k = 0; k < HS; k++) acc = fmaf(hgs[k], W[k*144 + o], acc);
        if (idx < 144) pG[o] = acc; else pR[o] = acc;
    }
    __syncthreads();
    if (tid < NH) {
        int h = tid, gid = s*NH + h;
        float g0 = pG[0*16+h], g1 = pG[1*16+h], g2 = pG[2*16+h], g3 = pG[3*16+h];
        float g4 = pG[4*16+h], g5 = pG[5*16+h], g7 = pG[7*16+h], g8 = pG[8*16+h];
        g_prm[0][gid] = sigf(g0);
        g_prm[1][gid] = sigf(g1);
        g_prm[2][gid] = sigf(g2);
        g_prm[3][gid] = sigf(g3);
        float t = sigf(g4) * 10.f; g_prm[4][gid] = t*t*t;
        g_prm[5][gid] = fmaxf(g5, 0.f) * 0.1f;
        g_prm[6][gid] = fminf(fmaxf(g7*(1.f/6.f) + 0.5f, 0.f), 1.f) * 0.5f;
        g_prm[7][gid] = fmaxf(g8, 0.f);
        // ga = softmax over heads of g(6)
        float m = -1e30f;
#pragma unroll
        for (int i = 0; i < 16; i++) m = fmaxf(m, pG[6*16+i]);
        float sum = 0.f;
#pragma unroll
        for (int i = 0; i < 16; i++) sum += expf(pG[6*16+i] - m);
        g_prm[8][gid] = expf(pG[6*16+h] - m) / sum;
        // wr: softmax over 9, cumsum, fold, normalize first 8
        float r[9];
        float rm = -1e30f;
#pragma unroll
        for (int i = 0; i < 9; i++) { r[i] = pR[h*9 + i]; rm = fmaxf(rm, r[i]); }
        float rs = 0.f;
#pragma unroll
        for (int i = 0; i < 9; i++) { r[i] = expf(r[i] - rm); rs += r[i]; }
        float inv = 1.f / rs;
        float c = 0.f, w[8], ws = 0.f;
#pragma unroll
        for (int i = 0; i < 8; i++) {
            float si = r[i] * inv;
            c += si;
            float wi = fminf(c, 1.f - c + si);
            w[i] = wi; ws += wi;
        }
        float wsi = 1.f / ws;
#pragma unroll
        for (int i = 0; i < 8; i++) g_wr[gid*NR + i] = w[i] * wsi;
    }
}

// ---------------- kernel 3: big K-param MLP (block per site, f32x2) ----------------
__device__ __forceinline__ void stor_k(int base, int o, float v) {
    int h = o & 15;
    if (o < 16)       g_km[base + h] = __expf(v);
    else if (o < 32)  g_ki[base + h] = fmaxf(v, 0.f);
    else              g_ke[base + h] = __expf(v);
}

__global__ void __launch_bounds__(512, 1) k_kparam(
        const float* __restrict__ x, const float* __restrict__ W_kin,
        const float* __restrict__ W_kout, const float* __restrict__ b_kout) {
    extern __shared__ float sm[];
    float* hsh = sm;                       // TILE_T * HROW
    float* wt  = sm + TILE_T*HROW;         // 48 * HROW (transposed W_kout)
    float* ft  = wt + NO*HROW;             // TILE_T * 4
    int s = blockIdx.x, tid = threadIdx.x;

    // transpose W_kout into shared: wt[o][k]
    for (int idx = tid; idx < HS*NO; idx += 512) {
        int k = idx / NO, o = idx - k*NO;
        wt[o*HROW + k] = W_kout[idx];
    }
    // phase-1 identity: thread owns hidden unit kh, half th of the t-tile
    int kh = tid & 255;
    int th = tid >> 8;   // 0 or 1
    float zb  = g_zbase[s*HS + kh];
    float wk0 = W_kin[0*HS + kh], wk1 = W_kin[1*HS + kh];
    float wk2 = W_kin[2*HS + kh], wk3 = W_kin[3*HS + kh];

    // phase-2 identity: og (output group of 3), tg (t group of 4)
    int og = tid & 15, tg = tid >> 4;   // tg 0..31
    int ob = og * 3;
    float bo0 = b_kout[ob], bo1 = b_kout[ob+1], bo2 = b_kout[ob+2];
    const ulonglong2* w0 = (const ulonglong2*)(wt + (ob+0)*HROW);
    const ulonglong2* w1 = (const ulonglong2*)(wt + (ob+1)*HROW);
    const ulonglong2* w2 = (const ulonglong2*)(wt + (ob+2)*HROW);
    const ulonglong2* h0 = (const ulonglong2*)(hsh + (tg*4+0)*HROW);
    const ulonglong2* h1 = (const ulonglong2*)(hsh + (tg*4+1)*HROW);
    const ulonglong2* h2 = (const ulonglong2*)(hsh + (tg*4+2)*HROW);
    const ulonglong2* h3 = (const ulonglong2*)(hsh + (tg*4+3)*HROW);

    for (int tb = 0; tb < NT; tb += TILE_T) {
        __syncthreads();   // previous tile fully consumed
        if (tid < TILE_T) {
            int t = tb + tid;
            if (t < NT) {
                const float* xr = x + (size_t)(t*NS + s) * 6;
                float Prcp = xr[0], Evp = xr[1], T1 = xr[2], T2 = xr[3];
                ft[tid*4+0] = T1; ft[tid*4+1] = T2;
                ft[tid*4+2] = xr[4]; ft[tid*4+3] = xr[5];
                float fl = fminf(fmaxf(T2 / (T2 - T1 + 1e-5f), 0.f), 1.f);
                g_Pl[t*NS + s] = Prcp * fl;
                g_Ps[t*NS + s] = Prcp * (1.f - fl);
                g_Ev[t*NS + s] = Evp;
            } else {
                ft[tid*4+0] = 0.f; ft[tid*4+1] = 0.f;
                ft[tid*4+2] = 0.f; ft[tid*4+3] = 0.f;
            }
        }
        __syncthreads();
        // phase 1: hidden tile (each thread: 64 timesteps of its hidden unit)
#pragma unroll 4
        for (int i = 0; i < 64; i++) {
            int tl = th*64 + i;
            float z = zb;
            z = fmaf(ft[tl*4+0], wk0, z);
            z = fmaf(ft[tl*4+1], wk1, z);
            z = fmaf(ft[tl*4+2], wk2, z);
            z = fmaf(ft[tl*4+3], wk3, z);
            hsh[tl*HROW + kh] = ((tb + tl) < NT) ? tanh_fast(z) : 0.f;
        }
        __syncthreads();
        // phase 2: 4 timesteps x 3 outputs per thread, f32x2 packed FMA
        unsigned long long acc[24];
#pragma unroll
        for (int i = 0; i < 24; i++) acc[i] = 0ULL;
#pragma unroll 8
        for (int k4 = 0; k4 < HS/4; k4++) {
            ulonglong2 ha = h0[k4], hb = h1[k4], hc = h2[k4], hd = h3[k4];
            ulonglong2 p = w0[k4], q = w1[k4], r = w2[k4];
            FFMA2(acc[ 0], ha.x, p.x); FFMA2(acc[ 1], ha.y, p.y);
            FFMA2(acc[ 2], ha.x, q.x); FFMA2(acc[ 3], ha.y, q.y);
            FFMA2(acc[ 4], ha.x, r.x); FFMA2(acc[ 5], ha.y, r.y);
            FFMA2(acc[ 6], hb.x, p.x); FFMA2(acc[ 7], hb.y, p.y);
            FFMA2(acc[ 8], hb.x, q.x); FFMA2(acc[ 9], hb.y, q.y);
            FFMA2(acc[10], hb.x, r.x); FFMA2(acc[11], hb.y, r.y);
            FFMA2(acc[12], hc.x, p.x); FFMA2(acc[13], hc.y, p.y);
            FFMA2(acc[14], hc.x, q.x); FFMA2(acc[15], hc.y, q.y);
            FFMA2(acc[16], hc.x, r.x); FFMA2(acc[17], hc.y, r.y);
            FFMA2(acc[18], hd.x, p.x); FFMA2(acc[19], hd.y, p.y);
            FFMA2(acc[20], hd.x, q.x); FFMA2(acc[21], hd.y, q.y);
            FFMA2(acc[22], hd.x, r.x); FFMA2(acc[23], hd.y, r.y);
        }
#pragma unroll
        for (int i = 0; i < 4; i++) {
            int t = tb + tg*4 + i;
            if (t < NT) {
                int base = t*NSNH + s*NH;
                float v0 = psum(acc[i*6+0]) + psum(acc[i*6+1]) + bo0;
                float v1 = psum(acc[i*6+2]) + psum(acc[i*6+3]) + bo1;
                float v2 = psum(acc[i*6+4]) + psum(acc[i*6+5]) + bo2;
                stor_k(base, ob+0, v0);
                stor_k(base, ob+1, v1);
                stor_k(base, ob+2, v2);
            }
        }
    }
}

// ---------------- kernel 4: fused scan + routing conv, 8-deep prefetch ----------------
__global__ void __launch_bounds__(128) k_scan(float* __restrict__ out) {
    int gid = blockIdx.x * blockDim.x + threadIdx.x;   // = s*NH + h
    int site = gid >> 4, h = gid & 15;
    float kp = g_prm[0][gid], ksg = g_prm[1][gid], kd = g_prm[2][gid];
    float gd = g_prm[3][gid], gl = g_prm[4][gid], qb = g_prm[5][gid];
    float gi = g_prm[6][gid], ge = g_prm[7][gid], ga = g_prm[8][gid];
    const float4* wrp = (const float4*)(g_wr + gid*NR);
    float4 wa = wrp[0], wb = wrp[1];
    float wrv[8] = {wa.x, wa.y, wa.z, wa.w, wb.x, wb.y, wb.z, wb.w};

    float A[8];
#pragma unroll
    for (int j = 0; j < 8; j++) A[j] = 0.f;
    float Sf = 0.f, Ss = 0.f, Sg = 0.f;

    // 8-deep prefetch ring
    float bkm[8], bki[8], bke[8], bPs[8], bPl[8], bEv[8];
#pragma unroll
    for (int i = 0; i < 8; i++) {
        bkm[i] = g_km[i*NSNH + gid];
        bki[i] = g_ki[i*NSNH + gid];
        bke[i] = g_ke[i*NSNH + gid];
        bPs[i] = g_Ps[i*NS + site];
        bPl[i] = g_Pl[i*NS + site];
        bEv[i] = g_Ev[i*NS + site];
    }

    for (int t = 0; t < NT; t += 8) {
#pragma unroll
        for (int i = 0; i < 8; i++) {
            int tc = t + i;
            float kmt = bkm[i], kit = bki[i], ket = bke[i];
            float Pst = bPs[i], Plt = bPl[i], Evt = bEv[i];
            int tp = tc + 8;
            if (tp < NT) {
                bkm[i] = g_km[tp*NSNH + gid];
                bki[i] = g_ki[tp*NSNH + gid];
                bke[i] = g_ke[tp*NSNH + gid];
                bPs[i] = g_Ps[tp*NS + site];
                bPl[i] = g_Pl[tp*NS + site];
                bEv[i] = g_Ev[tp*NS + site];
            }

            Sf += Pst;
            float qf = fminf(Sf, kmt); Sf -= qf;
            float inflow = qf + Plt;
            float qd = inflow * gi;
            Ss += inflow * (1.f - gi);
            float E = fminf(fmaxf(Ss, 0.f), Evt * ket * ge); Ss -= E;
            float qi = fminf(kit, fmaxf(Ss, 0.f)); Ss -= qi;
            float qp = kp * fmaxf(Ss - gl, 0.f);
            float qsa = ksg * fminf(fmaxf(Ss, 0.f), gl);
            Ss -= qp + qsa;
            Sg += qsa * gd;
            float qg = fmaf(kd, Sg, qb); Sg *= (1.f - kd);
            float q = qp + qsa * (1.f - gd) + qg + qd + qi;

#pragma unroll
            for (int j = 0; j < 8; j++) A[j] = fmaf(q, wrv[j], A[j]);

            if (tc >= NR - 1) {
                float v = A[0] * ga;
                v += __shfl_xor_sync(0xffffffffu, v, 1);
                v += __shfl_xor_sync(0xffffffffu, v, 2);
                v += __shfl_xor_sync(0xffffffffu, v, 4);
                v += __shfl_xor_sync(0xffffffffu, v, 8);
                if (h == 0) out[(tc - (NR-1))*NS + site] = v;
            }
#pragma unroll
            for (int j = 0; j < 7; j++) A[j] = A[j+1];
            A[7] = 0.f;
        }
    }
}

// ---------------- launch ----------------
extern "C" void kernel_launch(void* const* d_in, const int* in_sizes, int n_in,
                              void* d_out, int out_size) {
    const float* x      = (const float*)d_in[0];
    const float* xc     = (const float*)d_in[1];
    const float* W_fc   = (const float*)d_in[2];
    const float* b_fc   = (const float*)d_in[3];
    const float* W_r    = (const float*)d_in[4];
    const float* b_r    = (const float*)d_in[5];
    const float* W_g    = (const float*)d_in[6];
    const float* b_g    = (const float*)d_in[7];
    const float* W_kin  = (const float*)d_in[8];
    const float* b_kin  = (const float*)d_in[9];
    const float* W_kout = (const float*)d_in[10];
    const float* b_kout = (const float*)d_in[11];
    float* out = (float*)d_out;

    k_state<<<NS, HS>>>(xc, W_fc, b_fc, b_kin);
    k_params<<<NS, 256>>>(W_r, b_r, W_g, b_g);

    size_t smem = (size_t)(TILE_T*HROW + NO*HROW + TILE_T*4) * sizeof(float); // 185,088 B
    cudaFuncSetAttribute(k_kparam, cudaFuncAttributeMaxDynamicSharedMemorySize, (int)smem);
    k_kparam<<<NS, 512, smem>>>(x, W_kin, W_kout, b_kout);

    k_scan<<<(NS*NH)/128, 128>>>(out);
}

// round 4
// speedup vs baseline: 2.5363x; 1.9077x over previous
#include <cuda_runtime.h>
#include <cuda_bf16.h>
#include <cstdint>

#define NT   1000
#define NS   2048
#define NH   16
#define NR   8
#define HS   256
#define NG   32
#define NO   48
#define NSNH (NS*NH)
#define TILE_T 128
#define NTILES 8
#define STRIDE_H 560          // bytes per 256-bf16 row (35 x 16B -> conflict-free ldmatrix)

// ---- dynamic smem byte layout (k_kparam) ----
#define OF_HH 0
#define OF_HL (OF_HH + 128*STRIDE_H)          // 71680
#define OF_WH (OF_HL + 128*STRIDE_H)          // 143360
#define OF_WL (OF_WH + 48*STRIDE_H)           // 170240
#define OF_FT (OF_WL + 48*STRIDE_H)           // 197120
#define OF_ZB (OF_FT + 128*16)                // 199168
#define OF_WK (OF_ZB + 1024)                  // 200192
#define SMEM_BYTES (OF_WK + 4096)             // 204288

// ---------------- device scratch ----------------
__device__ float g_zbase[NS*HS];
__device__ float g_hg[NS*HS];
__device__ float g_prm[9][NSNH];
__device__ float g_wr[NSNH*NR];
__device__ float g_km[(size_t)NS*NT*NH];   // [s][t][h]
__device__ float g_ki[(size_t)NS*NT*NH];
__device__ float g_ke[(size_t)NS*NT*NH];
__device__ float g_Ps[NS*NT];              // [s][t]
__device__ float g_Pl[NS*NT];
__device__ float g_Ev[NS*NT];

__device__ __forceinline__ uint32_t smem_u32(const void* p) {
    uint32_t a;
    asm("{ .reg .u64 t; cvta.to.shared.u64 t, %1; cvt.u32.u64 %0, t; }" : "=r"(a) : "l"(p));
    return a;
}
__device__ __forceinline__ float tanh_fast(float x) {
    float y; asm("tanh.approx.f32 %0, %1;" : "=f"(y) : "f"(x)); return y;
}
__device__ __forceinline__ float sigf(float v) { return 1.f / (1.f + expf(-v)); }
__device__ __forceinline__ uint32_t packbf(float a, float b) {
    __nv_bfloat162 p = __floats2bfloat162_rn(a, b);
    return *reinterpret_cast<uint32_t*>(&p);
}

#define LDMATRIX_X4(r0,r1,r2,r3, addr) \
    asm volatile("ldmatrix.sync.aligned.m8n8.x4.shared.b16 {%0,%1,%2,%3}, [%4];" \
        : "=r"(r0),"=r"(r1),"=r"(r2),"=r"(r3) : "r"(addr))

#define MMA16816(c, a0,a1,a2,a3, b0,b1) \
    asm volatile("mma.sync.aligned.m16n8k16.row.col.f32.bf16.bf16.f32 " \
        "{%0,%1,%2,%3}, {%4,%5,%6,%7}, {%8,%9}, {%0,%1,%2,%3};" \
        : "+f"((c)[0]),"+f"((c)[1]),"+f"((c)[2]),"+f"((c)[3]) \
        : "r"(a0),"r"(a1),"r"(a2),"r"(a3), "r"(b0),"r"(b1))

// ---------------- kernel 1: state = xc@W_fc + b_fc ----------------
__global__ void k_state(const float* __restrict__ xc, const float* __restrict__ W_fc,
                        const float* __restrict__ b_fc, const float* __restrict__ b_kin) {
    int s = blockIdx.x, j = threadIdx.x;
    __shared__ float xcs[NG];
    if (j < NG) xcs[j] = xc[s*NG + j];
    __syncthreads();
    float acc = b_fc[j];
#pragma unroll
    for (int g = 0; g < NG; g++) acc = fmaf(xcs[g], W_fc[g*HS + j], acc);
    g_zbase[s*HS + j] = acc + b_kin[j];
    g_hg[s*HS + j]    = tanhf(acc);
}

// ---------------- kernel 2: per-site gate params + routing weights ----------------
__global__ void k_params(const float* __restrict__ W_r, const float* __restrict__ b_r,
                         const float* __restrict__ W_g, const float* __restrict__ b_g) {
    int s = blockIdx.x, tid = threadIdx.x;
    __shared__ float hgs[HS];
    __shared__ float pG[144], pR[144];
    hgs[tid] = g_hg[s*HS + tid];
    __syncthreads();
    for (int idx = tid; idx < 288; idx += 256) {
        int o = (idx < 144) ? idx : idx - 144;
        const float* W = (idx < 144) ? W_g : W_r;
        float acc = (idx < 144) ? b_g[o] : b_r[o];
#pragma unroll 8
        for (int k = 0; k < HS; k++) acc = fmaf(hgs[k], W[k*144 + o], acc);
        if (idx < 144) pG[o] = acc; else pR[o] = acc;
    }
    __syncthreads();
    if (tid < NH) {
        int h = tid, gid = s*NH + h;
        g_prm[0][gid] = sigf(pG[0*16+h]);
        g_prm[1][gid] = sigf(pG[1*16+h]);
        g_prm[2][gid] = sigf(pG[2*16+h]);
        g_prm[3][gid] = sigf(pG[3*16+h]);
        float t = sigf(pG[4*16+h]) * 10.f; g_prm[4][gid] = t*t*t;
        g_prm[5][gid] = fmaxf(pG[5*16+h], 0.f) * 0.1f;
        g_prm[6][gid] = fminf(fmaxf(pG[7*16+h]*(1.f/6.f) + 0.5f, 0.f), 1.f) * 0.5f;
        g_prm[7][gid] = fmaxf(pG[8*16+h], 0.f);
        float m = -1e30f;
#pragma unroll
        for (int i = 0; i < 16; i++) m = fmaxf(m, pG[6*16+i]);
        float sum = 0.f;
#pragma unroll
        for (int i = 0; i < 16; i++) sum += expf(pG[6*16+i] - m);
        g_prm[8][gid] = expf(pG[6*16+h] - m) / sum;
        float r[9]; float rm = -1e30f;
#pragma unroll
        for (int i = 0; i < 9; i++) { r[i] = pR[h*9 + i]; rm = fmaxf(rm, r[i]); }
        float rs = 0.f;
#pragma unroll
        for (int i = 0; i < 9; i++) { r[i] = expf(r[i] - rm); rs += r[i]; }
        float inv = 1.f / rs;
        float c = 0.f, w[8], ws = 0.f;
#pragma unroll
        for (int i = 0; i < 8; i++) {
            float si = r[i] * inv; c += si;
            float wi = fminf(c, 1.f - c + si);
            w[i] = wi; ws += wi;
        }
        float wsi = 1.f / ws;
#pragma unroll
        for (int i = 0; i < 8; i++) g_wr[gid*NR + i] = w[i] * wsi;
    }
}

// ---------------- kernel 3: K-param MLP via mma.sync bf16 3-pass ----------------
__global__ void __launch_bounds__(256, 1) k_kparam(
        const float* __restrict__ x, const float* __restrict__ W_kin,
        const float* __restrict__ W_kout, const float* __restrict__ b_kout) {
    extern __shared__ char sm[];
    uint32_t smb = smem_u32(sm);
    float* ft  = (float*)(sm + OF_FT);
    float* zbs = (float*)(sm + OF_ZB);
    float* wks = (float*)(sm + OF_WK);    // [k][4]
    int s = blockIdx.x, tid = threadIdx.x;
    int w = tid >> 5, lane = tid & 31;

    // ---- one-time setup ----
    zbs[tid] = g_zbase[s*HS + tid];
    for (int idx = tid; idx < 4*HS; idx += 256) {
        int f = idx >> 8, k = idx & 255;
        wks[k*4 + f] = W_kin[idx];
    }
    // W_kout split into bf16 hi/lo, stored transposed [n][k]
    for (int idx = tid; idx < HS*NO; idx += 256) {
        int k = idx / NO, n = idx - k*NO;
        float wv = W_kout[idx];
        __nv_bfloat16 hi = __float2bfloat16(wv);
        __nv_bfloat16 lo = __float2bfloat16(wv - __bfloat162float(hi));
        *(__nv_bfloat16*)(sm + OF_WH + n*STRIDE_H + k*2) = hi;
        *(__nv_bfloat16*)(sm + OF_WL + n*STRIDE_H + k*2) = lo;
    }

    // h-compute identity: thread -> (timestep tl, k-half)
    int tl = tid & 127;
    int kh = (tid >> 7) * 128;

    // mma identity: warp w -> m-tile rows [w*16, w*16+16)
    uint32_t a_hh_base = smb + OF_HH + (uint32_t)(w*16 + (lane & 15))*STRIDE_H + (uint32_t)(lane >> 4)*16;
    uint32_t a_hl_base = a_hh_base + (OF_HL - OF_HH);
    uint32_t b_wh_base = smb + OF_WH + (uint32_t)(lane >> 2)*STRIDE_H + (uint32_t)(lane & 3)*4;
    uint32_t b_wl_base = b_wh_base + (OF_WL - OF_WH);

    // epilogue biases (cols c0 = nt*8 + 2*(lane&3), c0+1)
    float bias0[6], bias1[6];
#pragma unroll
    for (int nt = 0; nt < 6; nt++) {
        int c0 = nt*8 + (lane & 3)*2;
        bias0[nt] = b_kout[c0];
        bias1[nt] = b_kout[c0+1];
    }
    __syncthreads();

    for (int tile = 0; tile < NTILES; tile++) {
        int tb = tile * TILE_T;
        // tile loader: features + precip partition
        if (tid < TILE_T) {
            int t = tb + tid;
            if (t < NT) {
                const float* xr = x + (size_t)(t*NS + s) * 6;
                float Prcp = xr[0], Evp = xr[1], T1 = xr[2], T2 = xr[3];
                ft[tid*4+0] = T1; ft[tid*4+1] = T2;
                ft[tid*4+2] = xr[4]; ft[tid*4+3] = xr[5];
                float fl = fminf(fmaxf(T2 / (T2 - T1 + 1e-5f), 0.f), 1.f);
                g_Pl[s*NT + t] = Prcp * fl;
                g_Ps[s*NT + t] = Prcp * (1.f - fl);
                g_Ev[s*NT + t] = Evp;
            } else {
                ft[tid*4+0] = 0.f; ft[tid*4+1] = 0.f; ft[tid*4+2] = 0.f; ft[tid*4+3] = 0.f;
            }
        }
        __syncthreads();

        // phase 1: tanh hidden (fp32) -> bf16 hi/lo tiles in smem
        {
            float4 fv = ((const float4*)ft)[tl];
            char* rowh = sm + OF_HH + tl*STRIDE_H + kh*2;
            char* rowl = sm + OF_HL + tl*STRIDE_H + kh*2;
#pragma unroll 2
            for (int k8 = 0; k8 < 128; k8 += 8) {
                uint32_t ph[4], pl[4];
#pragma unroll
                for (int j = 0; j < 4; j++) {
                    int k = kh + k8 + j*2;
                    float4 w0 = *(const float4*)(wks + 4*k);
                    float4 w1 = *(const float4*)(wks + 4*(k+1));
                    float z0 = fmaf(fv.x,w0.x, fmaf(fv.y,w0.y, fmaf(fv.z,w0.z, fmaf(fv.w,w0.w, zbs[k]))));
                    float z1 = fmaf(fv.x,w1.x, fmaf(fv.y,w1.y, fmaf(fv.z,w1.z, fmaf(fv.w,w1.w, zbs[k+1]))));
                    float h0 = tanh_fast(z0), h1 = tanh_fast(z1);
                    __nv_bfloat16 b0 = __float2bfloat16(h0), b1 = __float2bfloat16(h1);
                    ph[j] = packbf(h0, h1);
                    pl[j] = packbf(h0 - __bfloat162float(b0), h1 - __bfloat162float(b1));
                }
                *(uint4*)(rowh + k8*2) = make_uint4(ph[0], ph[1], ph[2], ph[3]);
                *(uint4*)(rowl + k8*2) = make_uint4(pl[0], pl[1], pl[2], pl[3]);
            }
        }
        __syncthreads();

        // phase 2: mma over 16 k-steps, 6 n-tiles, 3 passes
        float acc[6][4];
#pragma unroll
        for (int nt = 0; nt < 6; nt++) {
            acc[nt][0] = 0.f; acc[nt][1] = 0.f; acc[nt][2] = 0.f; acc[nt][3] = 0.f;
        }
#pragma unroll 4
        for (int ks = 0; ks < 16; ks++) {
            uint32_t koff = (uint32_t)ks * 32;
            uint32_t ah0, ah1, ah2, ah3, al0, al1, al2, al3;
            LDMATRIX_X4(ah0, ah1, ah2, ah3, a_hh_base + koff);
            LDMATRIX_X4(al0, al1, al2, al3, a_hl_base + koff);
#pragma unroll
            for (int nt = 0; nt < 6; nt++) {
                uint32_t bo = (uint32_t)(nt*8)*STRIDE_H + koff;
                uint32_t bh0 = *(const uint32_t*)(sm + (b_wh_base - smb) + bo);
                uint32_t bh1 = *(const uint32_t*)(sm + (b_wh_base - smb) + bo + 16);
                uint32_t bl0 = *(const uint32_t*)(sm + (b_wl_base - smb) + bo);
                uint32_t bl1 = *(const uint32_t*)(sm + (b_wl_base - smb) + bo + 16);
                MMA16816(acc[nt], ah0, ah1, ah2, ah3, bh0, bh1);
                MMA16816(acc[nt], ah0, ah1, ah2, ah3, bl0, bl1);
                MMA16816(acc[nt], al0, al1, al2, al3, bh0, bh1);
            }
        }

        // epilogue: bias + activation, direct float2 stores
        {
            int t0 = tb + w*16 + (lane >> 2);
            int t1 = t0 + 8;
#pragma unroll
            for (int nt = 0; nt < 6; nt++) {
                int c0 = nt*8 + (lane & 3)*2;     // even, pair stays in one output array
                int grp = c0 >> 4;                // 0 km, 1 ki, 2 ke
                int hcol = c0 & 15;
                float* arr = (grp == 0) ? g_km : (grp == 1) ? g_ki : g_ke;
                float v00 = acc[nt][0] + bias0[nt], v01 = acc[nt][1] + bias1[nt];
                float v10 = acc[nt][2] + bias0[nt], v11 = acc[nt][3] + bias1[nt];
                if (grp == 1) {
                    v00 = fmaxf(v00, 0.f); v01 = fmaxf(v01, 0.f);
                    v10 = fmaxf(v10, 0.f); v11 = fmaxf(v11, 0.f);
                } else {
                    v00 = __expf(v00); v01 = __expf(v01);
                    v10 = __expf(v10); v11 = __expf(v11);
                }
                if (t0 < NT)
                    *(float2*)(arr + ((size_t)s*NT + t0)*NH + hcol) = make_float2(v00, v01);
                if (t1 < NT)
                    *(float2*)(arr + ((size_t)s*NT + t1)*NH + hcol) = make_float2(v10, v11);
            }
        }
        __syncthreads();   // all mma reads done before next tile overwrites h tiles
    }
}

// ---------------- kernel 4: fused scan + routing conv, 8-deep prefetch ----------------
__global__ void __launch_bounds__(128) k_scan(float* __restrict__ out) {
    int gid = blockIdx.x * blockDim.x + threadIdx.x;   // = s*NH + h
    int site = gid >> 4, h = gid & 15;
    float kp = g_prm[0][gid], ksg = g_prm[1][gid], kd = g_prm[2][gid];
    float gd = g_prm[3][gid], gl = g_prm[4][gid], qb = g_prm[5][gid];
    float gi = g_prm[6][gid], ge = g_prm[7][gid], ga = g_prm[8][gid];
    const float4* wrp = (const float4*)(g_wr + gid*NR);
    float4 wa = wrp[0], wb = wrp[1];
    float wrv[8] = {wa.x, wa.y, wa.z, wa.w, wb.x, wb.y, wb.z, wb.w};

    float A[8];
#pragma unroll
    for (int j = 0; j < 8; j++) A[j] = 0.f;
    float Sf = 0.f, Ss = 0.f, Sg = 0.f;

    const float* pkm = g_km + ((size_t)site*NT)*NH + h;
    const float* pki = g_ki + ((size_t)site*NT)*NH + h;
    const float* pke = g_ke + ((size_t)site*NT)*NH + h;
    const float* pPs = g_Ps + site*NT;
    const float* pPl = g_Pl + site*NT;
    const float* pEv = g_Ev + site*NT;

    float bkm[8], bki[8], bke[8], bPs[8], bPl[8], bEv[8];
#pragma unroll
    for (int i = 0; i < 8; i++) {
        bkm[i] = pkm[i*NH]; bki[i] = pki[i*NH]; bke[i] = pke[i*NH];
        bPs[i] = pPs[i];    bPl[i] = pPl[i];    bEv[i] = pEv[i];
    }

    for (int t = 0; t < NT; t += 8) {
#pragma unroll
        for (int i = 0; i < 8; i++) {
            int tc = t + i;
            float kmt = bkm[i], kit = bki[i], ket = bke[i];
            float Pst = bPs[i], Plt = bPl[i], Evt = bEv[i];
            int tp = tc + 8;
            if (tp < NT) {
                bkm[i] = pkm[tp*NH]; bki[i] = pki[tp*NH]; bke[i] = pke[tp*NH];
                bPs[i] = pPs[tp];    bPl[i] = pPl[tp];    bEv[i] = pEv[tp];
            }

            Sf += Pst;
            float qf = fminf(Sf, kmt); Sf -= qf;
            float inflow = qf + Plt;
            float qd = inflow * gi;
            Ss += inflow * (1.f - gi);
            float E = fminf(fmaxf(Ss, 0.f), Evt * ket * ge); Ss -= E;
            float qi = fminf(kit, fmaxf(Ss, 0.f)); Ss -= qi;
            float qp = kp * fmaxf(Ss - gl, 0.f);
            float qsa = ksg * fminf(fmaxf(Ss, 0.f), gl);
            Ss -= qp + qsa;
            Sg += qsa * gd;
            float qg = fmaf(kd, Sg, qb); Sg *= (1.f - kd);
            float q = qp + qsa * (1.f - gd) + qg + qd + qi;

#pragma unroll
            for (int j = 0; j < 8; j++) A[j] = fmaf(q, wrv[j], A[j]);

            if (tc >= NR - 1) {
                float v = A[0] * ga;
                v += __shfl_xor_sync(0xffffffffu, v, 1);
                v += __shfl_xor_sync(0xffffffffu, v, 2);
                v += __shfl_xor_sync(0xffffffffu, v, 4);
                v += __shfl_xor_sync(0xffffffffu, v, 8);
                if (h == 0) out[(tc - (NR-1))*NS + site] = v;
            }
#pragma unroll
            for (int j = 0; j < 7; j++) A[j] = A[j+1];
            A[7] = 0.f;
        }
    }
}

// ---------------- launch ----------------
extern "C" void kernel_launch(void* const* d_in, const int* in_sizes, int n_in,
                              void* d_out, int out_size) {
    const float* x      = (const float*)d_in[0];
    const float* xc     = (const float*)d_in[1];
    const float* W_fc   = (const float*)d_in[2];
    const float* b_fc   = (const float*)d_in[3];
    const float* W_r    = (const float*)d_in[4];
    const float* b_r    = (const float*)d_in[5];
    const float* W_g    = (const float*)d_in[6];
    const float* b_g    = (const float*)d_in[7];
    const float* W_kin  = (const float*)d_in[8];
    const float* b_kin  = (const float*)d_in[9];
    const float* W_kout = (const float*)d_in[10];
    const float* b_kout = (const float*)d_in[11];
    float* out = (float*)d_out;

    k_state<<<NS, HS>>>(xc, W_fc, b_fc, b_kin);
    k_params<<<NS, 256>>>(W_r, b_r, W_g, b_g);

    cudaFuncSetAttribute(k_kparam, cudaFuncAttributeMaxDynamicSharedMemorySize, SMEM_BYTES);
    k_kparam<<<NS, 256, SMEM_BYTES>>>(x, W_kin, W_kout, b_kout);

    k_scan<<<(NS*NH)/128, 128>>>(out);
}

// round 5
// speedup vs baseline: 2.5781x; 1.0165x over previous
#include <cuda_runtime.h>
#include <cuda_bf16.h>
#include <cstdint>

#define NT   1000
#define NS   2048
#define NH   16
#define NR   8
#define HS   256
#define NG   32
#define NO   48
#define NSNH (NS*NH)
#define TILE_T 64
#define NSTEPS 16             // ceil(1000/64)
#define STRIDE_H 560          // bytes per 256-bf16 row (conflict-free ldmatrix/LDS)
#define ABUF_BYTES (TILE_T*STRIDE_H)   // 35840

// ---- dynamic smem byte layout (k_kparam) ----
#define OF_HH 0                                // 2 bufs x 35840
#define OF_HL (OF_HH + 2*ABUF_BYTES)           // 71680, 2 bufs
#define OF_WH (OF_HL + 2*ABUF_BYTES)           // 143360
#define OF_WL (OF_WH + 48*STRIDE_H)            // 170240
#define OF_FT (OF_WL + 48*STRIDE_H)            // 197120, 2 bufs x 64 x 16B
#define OF_ZB (OF_FT + 2*TILE_T*16)            // 199168
#define OF_WK (OF_ZB + 1024)                   // 200192
#define SMEM_BYTES (OF_WK + 4096)              // 204288

// ---------------- device scratch ----------------
__device__ float g_zbase[NS*HS];
__device__ float g_hg[NS*HS];
__device__ float g_prm[9][NSNH];
__device__ float g_wr[NSNH*NR];
__device__ float g_km[(size_t)NS*NT*NH];   // [s][t][h]
__device__ float g_ki[(size_t)NS*NT*NH];
__device__ float g_ke[(size_t)NS*NT*NH];
__device__ float g_Ps[NS*NT];              // [s][t]
__device__ float g_Pl[NS*NT];
__device__ float g_Ev[NS*NT];

__device__ __forceinline__ uint32_t smem_u32(const void* p) {
    uint32_t a;
    asm("{ .reg .u64 t; cvta.to.shared.u64 t, %1; cvt.u32.u64 %0, t; }" : "=r"(a) : "l"(p));
    return a;
}
__device__ __forceinline__ float tanh_fast(float x) {
    float y; asm("tanh.approx.f32 %0, %1;" : "=f"(y) : "f"(x)); return y;
}
__device__ __forceinline__ float sigf(float v) { return 1.f / (1.f + expf(-v)); }
__device__ __forceinline__ uint32_t packbf(float a, float b) {
    __nv_bfloat162 p = __floats2bfloat162_rn(a, b);
    return *reinterpret_cast<uint32_t*>(&p);
}

#define LDMATRIX_X4(r0,r1,r2,r3, addr) \
    asm volatile("ldmatrix.sync.aligned.m8n8.x4.shared.b16 {%0,%1,%2,%3}, [%4];" \
        : "=r"(r0),"=r"(r1),"=r"(r2),"=r"(r3) : "r"(addr))

#define MMA16816(c, a0,a1,a2,a3, b0,b1) \
    asm volatile("mma.sync.aligned.m16n8k16.row.col.f32.bf16.bf16.f32 " \
        "{%0,%1,%2,%3}, {%4,%5,%6,%7}, {%8,%9}, {%0,%1,%2,%3};" \
        : "+f"((c)[0]),"+f"((c)[1]),"+f"((c)[2]),"+f"((c)[3]) \
        : "r"(a0),"r"(a1),"r"(a2),"r"(a3), "r"(b0),"r"(b1))

#define BAR_PROD() asm volatile("bar.sync 1, 128;" ::: "memory")

// ---------------- kernel 1: state = xc@W_fc + b_fc ----------------
__global__ void k_state(const float* __restrict__ xc, const float* __restrict__ W_fc,
                        const float* __restrict__ b_fc, const float* __restrict__ b_kin) {
    int s = blockIdx.x, j = threadIdx.x;
    __shared__ float xcs[NG];
    if (j < NG) xcs[j] = xc[s*NG + j];
    __syncthreads();
    float acc = b_fc[j];
#pragma unroll
    for (int g = 0; g < NG; g++) acc = fmaf(xcs[g], W_fc[g*HS + j], acc);
    g_zbase[s*HS + j] = acc + b_kin[j];
    g_hg[s*HS + j]    = tanhf(acc);
}

// ---------------- kernel 2: per-site gate params + routing weights ----------------
__global__ void k_params(const float* __restrict__ W_r, const float* __restrict__ b_r,
                         const float* __restrict__ W_g, const float* __restrict__ b_g) {
    int s = blockIdx.x, tid = threadIdx.x;
    __shared__ float hgs[HS];
    __shared__ float pG[144], pR[144];
    hgs[tid] = g_hg[s*HS + tid];
    __syncthreads();
    for (int idx = tid; idx < 288; idx += 256) {
        int o = (idx < 144) ? idx : idx - 144;
        const float* W = (idx < 144) ? W_g : W_r;
        float acc = (idx < 144) ? b_g[o] : b_r[o];
#pragma unroll 8
        for (int k = 0; k < HS; k++) acc = fmaf(hgs[k], W[k*144 + o], acc);
        if (idx < 144) pG[o] = acc; else pR[o] = acc;
    }
    __syncthreads();
    if (tid < NH) {
        int h = tid, gid = s*NH + h;
        g_prm[0][gid] = sigf(pG[0*16+h]);
        g_prm[1][gid] = sigf(pG[1*16+h]);
        g_prm[2][gid] = sigf(pG[2*16+h]);
        g_prm[3][gid] = sigf(pG[3*16+h]);
        float t = sigf(pG[4*16+h]) * 10.f; g_prm[4][gid] = t*t*t;
        g_prm[5][gid] = fmaxf(pG[5*16+h], 0.f) * 0.1f;
        g_prm[6][gid] = fminf(fmaxf(pG[7*16+h]*(1.f/6.f) + 0.5f, 0.f), 1.f) * 0.5f;
        g_prm[7][gid] = fmaxf(pG[8*16+h], 0.f);
        float m = -1e30f;
#pragma unroll
        for (int i = 0; i < 16; i++) m = fmaxf(m, pG[6*16+i]);
        float sum = 0.f;
#pragma unroll
        for (int i = 0; i < 16; i++) sum += expf(pG[6*16+i] - m);
        g_prm[8][gid] = expf(pG[6*16+h] - m) / sum;
        float r[9]; float rm = -1e30f;
#pragma unroll
        for (int i = 0; i < 9; i++) { r[i] = pR[h*9 + i]; rm = fmaxf(rm, r[i]); }
        float rs = 0.f;
#pragma unroll
        for (int i = 0; i < 9; i++) { r[i] = expf(r[i] - rm); rs += r[i]; }
        float inv = 1.f / rs;
        float c = 0.f, w[8], ws = 0.f;
#pragma unroll
        for (int i = 0; i < 8; i++) {
            float si = r[i] * inv; c += si;
            float wi = fminf(c, 1.f - c + si);
            w[i] = wi; ws += wi;
        }
        float wsi = 1.f / ws;
#pragma unroll
        for (int i = 0; i < 8; i++) g_wr[gid*NR + i] = w[i] * wsi;
    }
}

// ---------------- kernel 3: warp-specialized K-param MLP ----------------
__global__ void __launch_bounds__(256, 1) k_kparam(
        const float* __restrict__ x, const float* __restrict__ W_kin,
        const float* __restrict__ W_kout, const float* __restrict__ b_kout) {
    extern __shared__ char sm[];
    uint32_t smb = smem_u32(sm);
    float* zbs = (float*)(sm + OF_ZB);
    float* wks = (float*)(sm + OF_WK);    // [k][4]
    int s = blockIdx.x, tid = threadIdx.x;
    int w = tid >> 5, lane = tid & 31;

    // ---- one-time setup (all threads) ----
    zbs[tid] = g_zbase[s*HS + tid];
    for (int idx = tid; idx < 4*HS; idx += 256) {
        int f = idx >> 8, k = idx & 255;
        wks[k*4 + f] = W_kin[idx];
    }
    for (int idx = tid; idx < HS*NO; idx += 256) {
        int k = idx / NO, n = idx - k*NO;
        float wv = W_kout[idx];
        __nv_bfloat16 hi = __float2bfloat16(wv);
        __nv_bfloat16 lo = __float2bfloat16(wv - __bfloat162float(hi));
        *(__nv_bfloat16*)(sm + OF_WH + n*STRIDE_H + k*2) = hi;
        *(__nv_bfloat16*)(sm + OF_WL + n*STRIDE_H + k*2) = lo;
    }
    __syncthreads();

    if (w < 4) {
        // ================= PRODUCER (threads 0..127) =================
        int pid = tid;                 // 0..127
        int tl  = pid & 63;            // timestep row in tile
        int kh  = (pid >> 6) * 128;    // k half

        for (int step = 0; step < NSTEPS; step++) {
            // produce tile 'step' into buf step&1  (prologue-free: produce then sync)
            int tb = step * TILE_T;
            int buf = step & 1;
            float* ft = (float*)(sm + OF_FT + buf * TILE_T * 16);
            if (pid < TILE_T) {
                int t = tb + pid;
                if (t < NT) {
                    const float* xr = x + (size_t)(t*NS + s) * 6;
                    float Prcp = xr[0], Evp = xr[1], T1 = xr[2], T2 = xr[3];
                    ft[pid*4+0] = T1; ft[pid*4+1] = T2;
                    ft[pid*4+2] = xr[4]; ft[pid*4+3] = xr[5];
                    float fl = fminf(fmaxf(T2 / (T2 - T1 + 1e-5f), 0.f), 1.f);
                    g_Pl[s*NT + t] = Prcp * fl;
                    g_Ps[s*NT + t] = Prcp * (1.f - fl);
                    g_Ev[s*NT + t] = Evp;
                } else {
                    ft[pid*4+0] = 0.f; ft[pid*4+1] = 0.f; ft[pid*4+2] = 0.f; ft[pid*4+3] = 0.f;
                }
            }
            BAR_PROD();
            float4 fv = ((const float4*)ft)[tl];
            char* rowh = sm + OF_HH + buf*ABUF_BYTES + tl*STRIDE_H + kh*2;
            char* rowl = sm + OF_HL + buf*ABUF_BYTES + tl*STRIDE_H + kh*2;
#pragma unroll 2
            for (int k8 = 0; k8 < 128; k8 += 8) {
                uint32_t ph[4], pl[4];
#pragma unroll
                for (int j = 0; j < 4; j++) {
                    int k = kh + k8 + j*2;
                    float4 w0 = *(const float4*)(wks + 4*k);
                    float4 w1 = *(const float4*)(wks + 4*(k+1));
                    float z0 = fmaf(fv.x,w0.x, fmaf(fv.y,w0.y, fmaf(fv.z,w0.z, fmaf(fv.w,w0.w, zbs[k]))));
                    float z1 = fmaf(fv.x,w1.x, fmaf(fv.y,w1.y, fmaf(fv.z,w1.z, fmaf(fv.w,w1.w, zbs[k+1]))));
                    float h0 = tanh_fast(z0), h1 = tanh_fast(z1);
                    __nv_bfloat16 b0 = __float2bfloat16(h0), b1 = __float2bfloat16(h1);
                    ph[j] = packbf(h0, h1);
                    pl[j] = packbf(h0 - __bfloat162float(b0), h1 - __bfloat162float(b1));
                }
                *(uint4*)(rowh + k8*2) = make_uint4(ph[0], ph[1], ph[2], ph[3]);
                *(uint4*)(rowl + k8*2) = make_uint4(pl[0], pl[1], pl[2], pl[3]);
            }
            __syncthreads();   // tile 'step' ready; consumers finished tile 'step-1'
        }
        __syncthreads();       // final consumer step
    } else {
        // ================= CONSUMER (threads 128..255, warps 4..7) =================
        int cw = w - 4;        // m-tile index 0..3
        uint32_t a_hh0 = smb + OF_HH + (uint32_t)(cw*16 + (lane & 15))*STRIDE_H + (uint32_t)(lane >> 4)*16;
        uint32_t a_hl0 = a_hh0 + (OF_HL - OF_HH);
        const char* b_wh = sm + OF_WH + (lane >> 2)*STRIDE_H + (lane & 3)*4;
        const char* b_wl = b_wh + (OF_WL - OF_WH);
        float bias0[6], bias1[6];
#pragma unroll
        for (int nt = 0; nt < 6; nt++) {
            int c0 = nt*8 + (lane & 3)*2;
            bias0[nt] = b_kout[c0];
            bias1[nt] = b_kout[c0+1];
        }

        __syncthreads();       // wait for tile 0
        for (int step = 0; step < NSTEPS; step++) {
            int tb = step * TILE_T;
            uint32_t abase_h = a_hh0 + (uint32_t)(step & 1)*ABUF_BYTES;
            uint32_t abase_l = a_hl0 + (uint32_t)(step & 1)*ABUF_BYTES;

            float acc[6][4];
#pragma unroll
            for (int nt = 0; nt < 6; nt++) {
                acc[nt][0] = 0.f; acc[nt][1] = 0.f; acc[nt][2] = 0.f; acc[nt][3] = 0.f;
            }
#pragma unroll 4
            for (int ks = 0; ks < 16; ks++) {
                uint32_t koff = (uint32_t)ks * 32;
                uint32_t ah0, ah1, ah2, ah3, al0, al1, al2, al3;
                LDMATRIX_X4(ah0, ah1, ah2, ah3, abase_h + koff);
                LDMATRIX_X4(al0, al1, al2, al3, abase_l + koff);
#pragma unroll
                for (int nt = 0; nt < 6; nt++) {
                    uint32_t bo = (uint32_t)(nt*8)*STRIDE_H + koff;
                    uint32_t bh0 = *(const uint32_t*)(b_wh + bo);
                    uint32_t bh1 = *(const uint32_t*)(b_wh + bo + 16);
                    uint32_t bl0 = *(const uint32_t*)(b_wl + bo);
                    uint32_t bl1 = *(const uint32_t*)(b_wl + bo + 16);
                    MMA16816(acc[nt], ah0, ah1, ah2, ah3, bh0, bh1);
                    MMA16816(acc[nt], ah0, ah1, ah2, ah3, bl0, bl1);
                    MMA16816(acc[nt], al0, al1, al2, al3, bh0, bh1);
                }
            }

            int t0 = tb + cw*16 + (lane >> 2);
            int t1 = t0 + 8;
#pragma unroll
            for (int nt = 0; nt < 6; nt++) {
                int c0 = nt*8 + (lane & 3)*2;
                int grp = c0 >> 4;
                int hcol = c0 & 15;
                float* arr = (grp == 0) ? g_km : (grp == 1) ? g_ki : g_ke;
                float v00 = acc[nt][0] + bias0[nt], v01 = acc[nt][1] + bias1[nt];
                float v10 = acc[nt][2] + bias0[nt], v11 = acc[nt][3] + bias1[nt];
                if (grp == 1) {
                    v00 = fmaxf(v00, 0.f); v01 = fmaxf(v01, 0.f);
                    v10 = fmaxf(v10, 0.f); v11 = fmaxf(v11, 0.f);
                } else {
                    v00 = __expf(v00); v01 = __expf(v01);
                    v10 = __expf(v10); v11 = __expf(v11);
                }
                if (t0 < NT)
                    *(float2*)(arr + ((size_t)s*NT + t0)*NH + hcol) = make_float2(v00, v01);
                if (t1 < NT)
                    *(float2*)(arr + ((size_t)s*NT + t1)*NH + hcol) = make_float2(v10, v11);
            }
            __syncthreads();   // done with this buf; producer may refill it
        }
    }
}

// ---------------- kernel 4: fused scan + routing conv, prefetch ring + L2 prefetch ----------------
__global__ void __launch_bounds__(128) k_scan(float* __restrict__ out) {
    int gid = blockIdx.x * blockDim.x + threadIdx.x;   // = s*NH + h
    int site = gid >> 4, h = gid & 15;
    float kp = g_prm[0][gid], ksg = g_prm[1][gid], kd = g_prm[2][gid];
    float gd = g_prm[3][gid], gl = g_prm[4][gid], qb = g_prm[5][gid];
    float gi = g_prm[6][gid], ge = g_prm[7][gid], ga = g_prm[8][gid];
    const float4* wrp = (const float4*)(g_wr + gid*NR);
    float4 wa = wrp[0], wb = wrp[1];
    float wrv[8] = {wa.x, wa.y, wa.z, wa.w, wb.x, wb.y, wb.z, wb.w};

    float A[8];
#pragma unroll
    for (int j = 0; j < 8; j++) A[j] = 0.f;
    float Sf = 0.f, Ss = 0.f, Sg = 0.f;

    const float* pkm = g_km + ((size_t)site*NT)*NH + h;
    const float* pki = g_ki + ((size_t)site*NT)*NH + h;
    const float* pke = g_ke + ((size_t)site*NT)*NH + h;
    const float* pPs = g_Ps + site*NT;
    const float* pPl = g_Pl + site*NT;
    const float* pEv = g_Ev + site*NT;

    float bkm[8], bki[8], bke[8], bPs[8], bPl[8], bEv[8];
#pragma unroll
    for (int i = 0; i < 8; i++) {
        bkm[i] = pkm[i*NH]; bki[i] = pki[i*NH]; bke[i] = pke[i*NH];
        bPs[i] = pPs[i];    bPl[i] = pPl[i];    bEv[i] = pEv[i];
    }

    for (int t = 0; t < NT; t += 8) {
#pragma unroll
        for (int i = 0; i < 8; i++) {
            int tc = t + i;
            float kmt = bkm[i], kit = bki[i], ket = bke[i];
            float Pst = bPs[i], Plt = bPl[i], Evt = bEv[i];
            int tp = tc + 8;
            if (tp < NT) {
                bkm[i] = pkm[tp*NH]; bki[i] = pki[tp*NH]; bke[i] = pke[tp*NH];
                bPs[i] = pPs[tp];    bPl[i] = pPl[tp];    bEv[i] = pEv[tp];
            }
            int tpp = tc + 24;
            if (tpp < NT) {
                asm volatile("prefetch.global.L2 [%0];" :: "l"(pkm + (size_t)tpp*NH));
                asm volatile("prefetch.global.L2 [%0];" :: "l"(pki + (size_t)tpp*NH));
                asm volatile("prefetch.global.L2 [%0];" :: "l"(pke + (size_t)tpp*NH));
            }

            Sf += Pst;
            float qf = fminf(Sf, kmt); Sf -= qf;
            float inflow = qf + Plt;
            float qd = inflow * gi;
            Ss += inflow * (1.f - gi);
            float E = fminf(fmaxf(Ss, 0.f), Evt * ket * ge); Ss -= E;
            float qi = fminf(kit, fmaxf(Ss, 0.f)); Ss -= qi;
            float qp = kp * fmaxf(Ss - gl, 0.f);
            float qsa = ksg * fminf(fmaxf(Ss, 0.f), gl);
            Ss -= qp + qsa;
            Sg += qsa * gd;
            float qg = fmaf(kd, Sg, qb); Sg *= (1.f - kd);
            float q = qp + qsa * (1.f - gd) + qg + qd + qi;

#pragma unroll
            for (int j = 0; j < 8; j++) A[j] = fmaf(q, wrv[j], A[j]);

            if (tc >= NR - 1) {
                float v = A[0] * ga;
                v += __shfl_xor_sync(0xffffffffu, v, 1);
                v += __shfl_xor_sync(0xffffffffu, v, 2);
                v += __shfl_xor_sync(0xffffffffu, v, 4);
                v += __shfl_xor_sync(0xffffffffu, v, 8);
                if (h == 0) out[(tc - (NR-1))*NS + site] = v;
            }
#pragma unroll
            for (int j = 0; j < 7; j++) A[j] = A[j+1];
            A[7] = 0.f;
        }
    }
}

// ---------------- launch ----------------
extern "C" void kernel_launch(void* const* d_in, const int* in_sizes, int n_in,
                              void* d_out, int out_size) {
    const float* x      = (const float*)d_in[0];
    const float* xc     = (const float*)d_in[1];
    const float* W_fc   = (const float*)d_in[2];
    const float* b_fc   = (const float*)d_in[3];
    const float* W_r    = (const float*)d_in[4];
    const float* b_r    = (const float*)d_in[5];
    const float* W_g    = (const float*)d_in[6];
    const float* b_g    = (const float*)d_in[7];
    const float* W_kin  = (const float*)d_in[8];
    const float* b_kin  = (const float*)d_in[9];
    const float* W_kout = (const float*)d_in[10];
    const float* b_kout = (const float*)d_in[11];
    float* out = (float*)d_out;

    k_state<<<NS, HS>>>(xc, W_fc, b_fc, b_kin);
    k_params<<<NS, 256>>>(W_r, b_r, W_g, b_g);

    cudaFuncSetAttribute(k_kparam, cudaFuncAttributeMaxDynamicSharedMemorySize, SMEM_BYTES);
    k_kparam<<<NS, 256, SMEM_BYTES>>>(x, W_kin, W_kout, b_kout);

    k_scan<<<(NS*NH)/128, 128>>>(out);
}

// round 6
// speedup vs baseline: 3.9840x; 1.5453x over previous
#include <cuda_runtime.h>
#include <cuda_bf16.h>
#include <cuda_fp16.h>
#include <cstdint>

#define NT   1000
#define NS   2048
#define NH   16
#define NR   8
#define HS   256
#define NG   32
#define NO   48
#define NSNH (NS*NH)
#define TILE_T 128
#define NTILES 8
#define STRIDE_H 560          // bytes per 256-fp16 row (conflict-free ldmatrix/LDS)

// ---- dynamic smem byte layout (k_kparam) ----
#define OF_H  0                               // 128 x 560 = 71680
#define OF_W  (OF_H + 128*STRIDE_H)           // 71680, 48 x 560 = 26880
#define OF_FT (OF_W + 48*STRIDE_H)            // 98560, 128 x 16
#define OF_ZB (OF_FT + TILE_T*16)             // 100608
#define OF_WK (OF_ZB + 1024)                  // 101632
#define SMEM_BYTES (OF_WK + 4096)             // 105728  -> 2 CTAs/SM

// ---------------- device scratch ----------------
__device__ float g_zbase[NS*HS];
__device__ float g_hg[NS*HS];
__device__ float g_prm[9][NSNH];
__device__ float g_wr[NSNH*NR];
__device__ __half g_k3[(size_t)NS*NT*48];  // [s][t][48]: 0..15 km, 16..31 ki, 32..47 ke
__device__ float g_Ps[NS*NT];              // [s][t]
__device__ float g_Pl[NS*NT];
__device__ float g_Ev[NS*NT];

__device__ __forceinline__ uint32_t smem_u32(const void* p) {
    uint32_t a;
    asm("{ .reg .u64 t; cvta.to.shared.u64 t, %1; cvt.u32.u64 %0, t; }" : "=r"(a) : "l"(p));
    return a;
}
__device__ __forceinline__ float tanh_fast(float x) {
    float y; asm("tanh.approx.f32 %0, %1;" : "=f"(y) : "f"(x)); return y;
}
__device__ __forceinline__ float sigf(float v) { return 1.f / (1.f + expf(-v)); }
__device__ __forceinline__ uint32_t packh2(float a, float b) {
    __half2 p = __floats2half2_rn(a, b);
    return *reinterpret_cast<uint32_t*>(&p);
}

#define LDMATRIX_X4(r0,r1,r2,r3, addr) \
    asm volatile("ldmatrix.sync.aligned.m8n8.x4.shared.b16 {%0,%1,%2,%3}, [%4];" \
        : "=r"(r0),"=r"(r1),"=r"(r2),"=r"(r3) : "r"(addr))

#define MMA16816F16(c, a0,a1,a2,a3, b0,b1) \
    asm volatile("mma.sync.aligned.m16n8k16.row.col.f32.f16.f16.f32 " \
        "{%0,%1,%2,%3}, {%4,%5,%6,%7}, {%8,%9}, {%0,%1,%2,%3};" \
        : "+f"((c)[0]),"+f"((c)[1]),"+f"((c)[2]),"+f"((c)[3]) \
        : "r"(a0),"r"(a1),"r"(a2),"r"(a3), "r"(b0),"r"(b1))

// ---------------- kernel 1: state = xc@W_fc + b_fc ----------------
__global__ void k_state(const float* __restrict__ xc, const float* __restrict__ W_fc,
                        const float* __restrict__ b_fc, const float* __restrict__ b_kin) {
    int s = blockIdx.x, j = threadIdx.x;
    __shared__ float xcs[NG];
    if (j < NG) xcs[j] = xc[s*NG + j];
    __syncthreads();
    float acc = b_fc[j];
#pragma unroll
    for (int g = 0; g < NG; g++) acc = fmaf(xcs[g], W_fc[g*HS + j], acc);
    g_zbase[s*HS + j] = acc + b_kin[j];
    g_hg[s*HS + j]    = tanhf(acc);
}

// ---------------- kernel 2: per-site gate params + routing weights ----------------
__global__ void k_params(const float* __restrict__ W_r, const float* __restrict__ b_r,
                         const float* __restrict__ W_g, const float* __restrict__ b_g) {
    int s = blockIdx.x, tid = threadIdx.x;
    __shared__ float hgs[HS];
    __shared__ float pG[144], pR[144];
    hgs[tid] = g_hg[s*HS + tid];
    __syncthreads();
    for (int idx = tid; idx < 288; idx += 256) {
        int o = (idx < 144) ? idx : idx - 144;
        const float* W = (idx < 144) ? W_g : W_r;
        float acc = (idx < 144) ? b_g[o] : b_r[o];
#pragma unroll 8
        for (int k = 0; k < HS; k++) acc = fmaf(hgs[k], W[k*144 + o], acc);
        if (idx < 144) pG[o] = acc; else pR[o] = acc;
    }
    __syncthreads();
    if (tid < NH) {
        int h = tid, gid = s*NH + h;
        g_prm[0][gid] = sigf(pG[0*16+h]);
        g_prm[1][gid] = sigf(pG[1*16+h]);
        g_prm[2][gid] = sigf(pG[2*16+h]);
        g_prm[3][gid] = sigf(pG[3*16+h]);
        float t = sigf(pG[4*16+h]) * 10.f; g_prm[4][gid] = t*t*t;
        g_prm[5][gid] = fmaxf(pG[5*16+h], 0.f) * 0.1f;
        g_prm[6][gid] = fminf(fmaxf(pG[7*16+h]*(1.f/6.f) + 0.5f, 0.f), 1.f) * 0.5f;
        g_prm[7][gid] = fmaxf(pG[8*16+h], 0.f);
        float m = -1e30f;
#pragma unroll
        for (int i = 0; i < 16; i++) m = fmaxf(m, pG[6*16+i]);
        float sum = 0.f;
#pragma unroll
        for (int i = 0; i < 16; i++) sum += expf(pG[6*16+i] - m);
        g_prm[8][gid] = expf(pG[6*16+h] - m) / sum;
        float r[9]; float rm = -1e30f;
#pragma unroll
        for (int i = 0; i < 9; i++) { r[i] = pR[h*9 + i]; rm = fmaxf(rm, r[i]); }
        float rs = 0.f;
#pragma unroll
        for (int i = 0; i < 9; i++) { r[i] = expf(r[i] - rm); rs += r[i]; }
        float inv = 1.f / rs;
        float c = 0.f, w[8], ws = 0.f;
#pragma unroll
        for (int i = 0; i < 8; i++) {
            float si = r[i] * inv; c += si;
            float wi = fminf(c, 1.f - c + si);
            w[i] = wi; ws += wi;
        }
        float wsi = 1.f / ws;
#pragma unroll
        for (int i = 0; i < 8; i++) g_wr[gid*NR + i] = w[i] * wsi;
    }
}

// ---------------- kernel 3: K-param MLP, single-pass fp16 mma, 2 CTAs/SM ----------------
__global__ void __launch_bounds__(256, 2) k_kparam(
        const float* __restrict__ x, const float* __restrict__ W_kin,
        const float* __restrict__ W_kout, const float* __restrict__ b_kout) {
    extern __shared__ char sm[];
    uint32_t smb = smem_u32(sm);
    float* ft  = (float*)(sm + OF_FT);
    float* zbs = (float*)(sm + OF_ZB);
    float* wks = (float*)(sm + OF_WK);    // [k][4]
    int s = blockIdx.x, tid = threadIdx.x;
    int w = tid >> 5, lane = tid & 31;

    // ---- one-time setup ----
    zbs[tid] = g_zbase[s*HS + tid];
    for (int idx = tid; idx < 4*HS; idx += 256) {
        int f = idx >> 8, k = idx & 255;
        wks[k*4 + f] = W_kin[idx];
    }
    // W_kout as fp16, transposed [n][k]
    for (int idx = tid; idx < HS*NO; idx += 256) {
        int k = idx / NO, n = idx - k*NO;
        *(__half*)(sm + OF_W + n*STRIDE_H + k*2) = __float2half(W_kout[idx]);
    }

    // phase-1 identity
    int tl = tid & 127;
    int kh = (tid >> 7) * 128;

    // mma identity: warp w -> m rows [w*16, w*16+16)
    uint32_t a_base = smb + OF_H + (uint32_t)(w*16 + (lane & 15))*STRIDE_H + (uint32_t)(lane >> 4)*16;
    const char* b_w = sm + OF_W + (lane >> 2)*STRIDE_H + (lane & 3)*4;

    float bias0[6], bias1[6];
#pragma unroll
    for (int nt = 0; nt < 6; nt++) {
        int c0 = nt*8 + (lane & 3)*2;
        bias0[nt] = b_kout[c0];
        bias1[nt] = b_kout[c0+1];
    }
    __syncthreads();

    for (int tile = 0; tile < NTILES; tile++) {
        int tb = tile * TILE_T;
        if (tid < TILE_T) {
            int t = tb + tid;
            if (t < NT) {
                const float* xr = x + (size_t)(t*NS + s) * 6;
                float Prcp = xr[0], Evp = xr[1], T1 = xr[2], T2 = xr[3];
                ft[tid*4+0] = T1; ft[tid*4+1] = T2;
                ft[tid*4+2] = xr[4]; ft[tid*4+3] = xr[5];
                float fl = fminf(fmaxf(T2 / (T2 - T1 + 1e-5f), 0.f), 1.f);
                g_Pl[s*NT + t] = Prcp * fl;
                g_Ps[s*NT + t] = Prcp * (1.f - fl);
                g_Ev[s*NT + t] = Evp;
            } else {
                ft[tid*4+0] = 0.f; ft[tid*4+1] = 0.f; ft[tid*4+2] = 0.f; ft[tid*4+3] = 0.f;
            }
        }
        __syncthreads();

        // phase 1: tanh hidden -> fp16 tile in smem
        {
            float4 fv = ((const float4*)ft)[tl];
            char* row = sm + OF_H + tl*STRIDE_H + kh*2;
#pragma unroll 2
            for (int k8 = 0; k8 < 128; k8 += 8) {
                uint32_t ph[4];
#pragma unroll
                for (int j = 0; j < 4; j++) {
                    int k = kh + k8 + j*2;
                    float4 w0 = *(const float4*)(wks + 4*k);
                    float4 w1 = *(const float4*)(wks + 4*(k+1));
                    float z0 = fmaf(fv.x,w0.x, fmaf(fv.y,w0.y, fmaf(fv.z,w0.z, fmaf(fv.w,w0.w, zbs[k]))));
                    float z1 = fmaf(fv.x,w1.x, fmaf(fv.y,w1.y, fmaf(fv.z,w1.z, fmaf(fv.w,w1.w, zbs[k+1]))));
                    ph[j] = packh2(tanh_fast(z0), tanh_fast(z1));
                }
                *(uint4*)(row + k8*2) = make_uint4(ph[0], ph[1], ph[2], ph[3]);
            }
        }
        __syncthreads();

        // phase 2: single-pass fp16 mma, 16 k-steps x 6 n-tiles
        float acc[6][4];
#pragma unroll
        for (int nt = 0; nt < 6; nt++) {
            acc[nt][0] = 0.f; acc[nt][1] = 0.f; acc[nt][2] = 0.f; acc[nt][3] = 0.f;
        }
#pragma unroll 4
        for (int ks = 0; ks < 16; ks++) {
            uint32_t koff = (uint32_t)ks * 32;
            uint32_t a0, a1, a2, a3;
            LDMATRIX_X4(a0, a1, a2, a3, a_base + koff);
#pragma unroll
            for (int nt = 0; nt < 6; nt++) {
                uint32_t bo = (uint32_t)(nt*8)*STRIDE_H + koff;
                uint32_t b0 = *(const uint32_t*)(b_w + bo);
                uint32_t b1 = *(const uint32_t*)(b_w + bo + 16);
                MMA16816F16(acc[nt], a0, a1, a2, a3, b0, b1);
            }
        }

        // epilogue: bias + activation, fp16 packed stores [s][t][48]
        {
            int t0 = tb + w*16 + (lane >> 2);
            int t1 = t0 + 8;
#pragma unroll
            for (int nt = 0; nt < 6; nt++) {
                int c0 = nt*8 + (lane & 3)*2;
                int grp = c0 >> 4;                // 0 km(exp), 1 ki(relu), 2 ke(exp)
                float v00 = acc[nt][0] + bias0[nt], v01 = acc[nt][1] + bias1[nt];
                float v10 = acc[nt][2] + bias0[nt], v11 = acc[nt][3] + bias1[nt];
                if (grp == 1) {
                    v00 = fmaxf(v00, 0.f); v01 = fmaxf(v01, 0.f);
                    v10 = fmaxf(v10, 0.f); v11 = fmaxf(v11, 0.f);
                } else {
                    v00 = __expf(v00); v01 = __expf(v01);
                    v10 = __expf(v10); v11 = __expf(v11);
                }
                if (t0 < NT)
                    *(__half2*)(g_k3 + ((size_t)s*NT + t0)*48 + c0) = __floats2half2_rn(v00, v01);
                if (t1 < NT)
                    *(__half2*)(g_k3 + ((size_t)s*NT + t1)*48 + c0) = __floats2half2_rn(v10, v11);
            }
        }
        __syncthreads();
    }
}

// ---------------- kernel 4: fused scan + routing conv, fp16 streams ----------------
__global__ void __launch_bounds__(128) k_scan(float* __restrict__ out) {
    int gid = blockIdx.x * blockDim.x + threadIdx.x;   // = s*NH + h
    int site = gid >> 4, h = gid & 15;
    float kp = g_prm[0][gid], ksg = g_prm[1][gid], kd = g_prm[2][gid];
    float gd = g_prm[3][gid], gl = g_prm[4][gid], qb = g_prm[5][gid];
    float gi = g_prm[6][gid], ge = g_prm[7][gid], ga = g_prm[8][gid];
    const float4* wrp = (const float4*)(g_wr + gid*NR);
    float4 wa = wrp[0], wb = wrp[1];
    float wrv[8] = {wa.x, wa.y, wa.z, wa.w, wb.x, wb.y, wb.z, wb.w};

    float A[8];
#pragma unroll
    for (int j = 0; j < 8; j++) A[j] = 0.f;
    float Sf = 0.f, Ss = 0.f, Sg = 0.f;

    const __half* pk = g_k3 + ((size_t)site*NT)*48 + h;
    const float* pPs = g_Ps + site*NT;
    const float* pPl = g_Pl + site*NT;
    const float* pEv = g_Ev + site*NT;

    float bkm[8], bki[8], bke[8], bPs[8], bPl[8], bEv[8];
#pragma unroll
    for (int i = 0; i < 8; i++) {
        bkm[i] = __half2float(pk[(size_t)i*48]);
        bki[i] = __half2float(pk[(size_t)i*48 + 16]);
        bke[i] = __half2float(pk[(size_t)i*48 + 32]);
        bPs[i] = pPs[i]; bPl[i] = pPl[i]; bEv[i] = pEv[i];
    }

    for (int t = 0; t < NT; t += 8) {
#pragma unroll
        for (int i = 0; i < 8; i++) {
            int tc = t + i;
            float kmt = bkm[i], kit = bki[i], ket = bke[i];
            float Pst = bPs[i], Plt = bPl[i], Evt = bEv[i];
            int tp = tc + 8;
            if (tp < NT) {
                bkm[i] = __half2float(pk[(size_t)tp*48]);
                bki[i] = __half2float(pk[(size_t)tp*48 + 16]);
                bke[i] = __half2float(pk[(size_t)tp*48 + 32]);
                bPs[i] = pPs[tp]; bPl[i] = pPl[tp]; bEv[i] = pEv[tp];
            }

            Sf += Pst;
            float qf = fminf(Sf, kmt); Sf -= qf;
            float inflow = qf + Plt;
            float qd = inflow * gi;
            Ss += inflow * (1.f - gi);
            float E = fminf(fmaxf(Ss, 0.f), Evt * ket * ge); Ss -= E;
            float qi = fminf(kit, fmaxf(Ss, 0.f)); Ss -= qi;
            float qp = kp * fmaxf(Ss - gl, 0.f);
            float qsa = ksg * fminf(fmaxf(Ss, 0.f), gl);
            Ss -= qp + qsa;
            Sg += qsa * gd;
            float qg = fmaf(kd, Sg, qb); Sg *= (1.f - kd);
            float q = qp + qsa * (1.f - gd) + qg + qd + qi;

#pragma unroll
            for (int j = 0; j < 8; j++) A[j] = fmaf(q, wrv[j], A[j]);

            if (tc >= NR - 1) {
                float v = A[0] * ga;
                v += __shfl_xor_sync(0xffffffffu, v, 1);
                v += __shfl_xor_sync(0xffffffffu, v, 2);
                v += __shfl_xor_sync(0xffffffffu, v, 4);
                v += __shfl_xor_sync(0xffffffffu, v, 8);
                if (h == 0) out[(tc - (NR-1))*NS + site] = v;
            }
#pragma unroll
            for (int j = 0; j < 7; j++) A[j] = A[j+1];
            A[7] = 0.f;
        }
    }
}

// ---------------- launch ----------------
extern "C" void kernel_launch(void* const* d_in, const int* in_sizes, int n_in,
                              void* d_out, int out_size) {
    const float* x      = (const float*)d_in[0];
    const float* xc     = (const float*)d_in[1];
    const float* W_fc   = (const float*)d_in[2];
    const float* b_fc   = (const float*)d_in[3];
    const float* W_r    = (const float*)d_in[4];
    const float* b_r    = (const float*)d_in[5];
    const float* W_g    = (const float*)d_in[6];
    const float* b_g    = (const float*)d_in[7];
    const float* W_kin  = (const float*)d_in[8];
    const float* b_kin  = (const float*)d_in[9];
    const float* W_kout = (const float*)d_in[10];
    const float* b_kout = (const float*)d_in[11];
    float* out = (float*)d_out;

    k_state<<<NS, HS>>>(xc, W_fc, b_fc, b_kin);
    k_params<<<NS, 256>>>(W_r, b_r, W_g, b_g);

    cudaFuncSetAttribute(k_kparam, cudaFuncAttributeMaxDynamicSharedMemorySize, SMEM_BYTES);
    k_kparam<<<NS, 256, SMEM_BYTES>>>(x, W_kin, W_kout, b_kout);

    k_scan<<<(NS*NH)/128, 128>>>(out);
}

// round 7
// speedup vs baseline: 4.4697x; 1.1219x over previous
#include <cuda_runtime.h>
#include <cuda_bf16.h>
#include <cuda_fp16.h>
#include <cstdint>

#define NT   1000
#define NS   2048
#define NH   16
#define NR   8
#define HS   256
#define NG   32
#define NO   48
#define NSNH (NS*NH)
#define TILE_T 128
#define NTILES 8
#define STRIDE_H 560          // bytes per 256-fp16 row (conflict-free ldmatrix/LDS)

// ---- dynamic smem byte layout (k_kparam) ----
#define OF_H  0                               // 128 x 560 = 71680
#define OF_W  (OF_H + 128*STRIDE_H)           // 71680, 48 x 560 = 26880
#define OF_FT (OF_W + 48*STRIDE_H)            // 98560, 128 x 16
#define OF_ZB (OF_FT + TILE_T*16)             // 100608
#define OF_WK (OF_ZB + 1024)                  // 101632
#define SMEM_BYTES (OF_WK + 4096)             // 105728  -> 2 CTAs/SM

// ---------------- device scratch ----------------
__device__ float g_zbase[NS*HS];
__device__ float g_hg[NS*HS];
__device__ float g_prm[9][NSNH];
__device__ float g_wr[NSNH*NR];
__device__ __half g_k3[(size_t)NS*48*NT];  // [s][c][t]: c 0..15 km, 16..31 ki, 32..47 ke
__device__ float g_Ps[NS*NT];              // [s][t]
__device__ float g_Pl[NS*NT];
__device__ float g_Ev[NS*NT];

__device__ __forceinline__ uint32_t smem_u32(const void* p) {
    uint32_t a;
    asm("{ .reg .u64 t; cvta.to.shared.u64 t, %1; cvt.u32.u64 %0, t; }" : "=r"(a) : "l"(p));
    return a;
}
__device__ __forceinline__ float tanh_fast(float x) {
    float y; asm("tanh.approx.f32 %0, %1;" : "=f"(y) : "f"(x)); return y;
}
__device__ __forceinline__ float sigf(float v) { return 1.f / (1.f + expf(-v)); }
__device__ __forceinline__ uint32_t packh2(float a, float b) {
    __half2 p = __floats2half2_rn(a, b);
    return *reinterpret_cast<uint32_t*>(&p);
}
// extract half i (0..7) of a uint4 as float — i must be compile-time after unroll
__device__ __forceinline__ float geth(const uint4& v, int i) {
    uint32_t w = (i < 2) ? v.x : (i < 4) ? v.y : (i < 6) ? v.z : v.w;
    __half2 h2 = *reinterpret_cast<const __half2*>(&w);
    return (i & 1) ? __high2float(h2) : __low2float(h2);
}
__device__ __forceinline__ float getf(const float4& a, const float4& b, int i) {
    const float4& v = (i < 4) ? a : b;
    int j = i & 3;
    return (j == 0) ? v.x : (j == 1) ? v.y : (j == 2) ? v.z : v.w;
}

#define LDMATRIX_X4(r0,r1,r2,r3, addr) \
    asm volatile("ldmatrix.sync.aligned.m8n8.x4.shared.b16 {%0,%1,%2,%3}, [%4];" \
        : "=r"(r0),"=r"(r1),"=r"(r2),"=r"(r3) : "r"(addr))

#define MMA16816F16(c, a0,a1,a2,a3, b0,b1) \
    asm volatile("mma.sync.aligned.m16n8k16.row.col.f32.f16.f16.f32 " \
        "{%0,%1,%2,%3}, {%4,%5,%6,%7}, {%8,%9}, {%0,%1,%2,%3};" \
        : "+f"((c)[0]),"+f"((c)[1]),"+f"((c)[2]),"+f"((c)[3]) \
        : "r"(a0),"r"(a1),"r"(a2),"r"(a3), "r"(b0),"r"(b1))

// ---------------- kernel 1: state = xc@W_fc + b_fc ----------------
__global__ void k_state(const float* __restrict__ xc, const float* __restrict__ W_fc,
                        const float* __restrict__ b_fc, const float* __restrict__ b_kin) {
    int s = blockIdx.x, j = threadIdx.x;
    __shared__ float xcs[NG];
    if (j < NG) xcs[j] = xc[s*NG + j];
    __syncthreads();
    float acc = b_fc[j];
#pragma unroll
    for (int g = 0; g < NG; g++) acc = fmaf(xcs[g], W_fc[g*HS + j], acc);
    g_zbase[s*HS + j] = acc + b_kin[j];
    g_hg[s*HS + j]    = tanhf(acc);
}

// ---------------- kernel 2: per-site gate params + routing weights ----------------
__global__ void k_params(const float* __restrict__ W_r, const float* __restrict__ b_r,
                         const float* __restrict__ W_g, const float* __restrict__ b_g) {
    int s = blockIdx.x, tid = threadIdx.x;
    __shared__ float hgs[HS];
    __shared__ float pG[144], pR[144];
    hgs[tid] = g_hg[s*HS + tid];
    __syncthreads();
    for (int idx = tid; idx < 288; idx += 256) {
        int o = (idx < 144) ? idx : idx - 144;
        const float* W = (idx < 144) ? W_g : W_r;
        float acc = (idx < 144) ? b_g[o] : b_r[o];
#pragma unroll 8
        for (int k = 0; k < HS; k++) acc = fmaf(hgs[k], W[k*144 + o], acc);
        if (idx < 144) pG[o] = acc; else pR[o] = acc;
    }
    __syncthreads();
    if (tid < NH) {
        int h = tid, gid = s*NH + h;
        g_prm[0][gid] = sigf(pG[0*16+h]);
        g_prm[1][gid] = sigf(pG[1*16+h]);
        g_prm[2][gid] = sigf(pG[2*16+h]);
        g_prm[3][gid] = sigf(pG[3*16+h]);
        float t = sigf(pG[4*16+h]) * 10.f; g_prm[4][gid] = t*t*t;
        g_prm[5][gid] = fmaxf(pG[5*16+h], 0.f) * 0.1f;
        g_prm[6][gid] = fminf(fmaxf(pG[7*16+h]*(1.f/6.f) + 0.5f, 0.f), 1.f) * 0.5f;
        g_prm[7][gid] = fmaxf(pG[8*16+h], 0.f);
        float m = -1e30f;
#pragma unroll
        for (int i = 0; i < 16; i++) m = fmaxf(m, pG[6*16+i]);
        float sum = 0.f;
#pragma unroll
        for (int i = 0; i < 16; i++) sum += expf(pG[6*16+i] - m);
        g_prm[8][gid] = expf(pG[6*16+h] - m) / sum;
        float r[9]; float rm = -1e30f;
#pragma unroll
        for (int i = 0; i < 9; i++) { r[i] = pR[h*9 + i]; rm = fmaxf(rm, r[i]); }
        float rs = 0.f;
#pragma unroll
        for (int i = 0; i < 9; i++) { r[i] = expf(r[i] - rm); rs += r[i]; }
        float inv = 1.f / rs;
        float c = 0.f, w[8], ws = 0.f;
#pragma unroll
        for (int i = 0; i < 8; i++) {
            float si = r[i] * inv; c += si;
            float wi = fminf(c, 1.f - c + si);
            w[i] = wi; ws += wi;
        }
        float wsi = 1.f / ws;
#pragma unroll
        for (int i = 0; i < 8; i++) g_wr[gid*NR + i] = w[i] * wsi;
    }
}

// ---------------- kernel 3: K-param MLP, single-pass fp16 mma, 2 CTAs/SM ----------------
__global__ void __launch_bounds__(256, 2) k_kparam(
        const float* __restrict__ x, const float* __restrict__ W_kin,
        const float* __restrict__ W_kout, const float* __restrict__ b_kout) {
    extern __shared__ char sm[];
    uint32_t smb = smem_u32(sm);
    float* ft  = (float*)(sm + OF_FT);
    float* zbs = (float*)(sm + OF_ZB);
    float* wks = (float*)(sm + OF_WK);    // [k][4]
    int s = blockIdx.x, tid = threadIdx.x;
    int w = tid >> 5, lane = tid & 31;

    // ---- one-time setup ----
    zbs[tid] = g_zbase[s*HS + tid];
    for (int idx = tid; idx < 4*HS; idx += 256) {
        int f = idx >> 8, k = idx & 255;
        wks[k*4 + f] = W_kin[idx];
    }
    for (int idx = tid; idx < HS*NO; idx += 256) {
        int k = idx / NO, n = idx - k*NO;
        *(__half*)(sm + OF_W + n*STRIDE_H + k*2) = __float2half(W_kout[idx]);
    }

    int tl = tid & 127;
    int kh = (tid >> 7) * 128;

    uint32_t a_base = smb + OF_H + (uint32_t)(w*16 + (lane & 15))*STRIDE_H + (uint32_t)(lane >> 4)*16;
    const char* b_w = sm + OF_W + (lane >> 2)*STRIDE_H + (lane & 3)*4;

    float bias0[6], bias1[6];
#pragma unroll
    for (int nt = 0; nt < 6; nt++) {
        int c0 = nt*8 + (lane & 3)*2;
        bias0[nt] = b_kout[c0];
        bias1[nt] = b_kout[c0+1];
    }
    __syncthreads();

    for (int tile = 0; tile < NTILES; tile++) {
        int tb = tile * TILE_T;
        if (tid < TILE_T) {
            int t = tb + tid;
            if (t < NT) {
                const float* xr = x + (size_t)(t*NS + s) * 6;
                float Prcp = xr[0], Evp = xr[1], T1 = xr[2], T2 = xr[3];
                ft[tid*4+0] = T1; ft[tid*4+1] = T2;
                ft[tid*4+2] = xr[4]; ft[tid*4+3] = xr[5];
                float fl = fminf(fmaxf(T2 / (T2 - T1 + 1e-5f), 0.f), 1.f);
                g_Pl[s*NT + t] = Prcp * fl;
                g_Ps[s*NT + t] = Prcp * (1.f - fl);
                g_Ev[s*NT + t] = Evp;
            } else {
                ft[tid*4+0] = 0.f; ft[tid*4+1] = 0.f; ft[tid*4+2] = 0.f; ft[tid*4+3] = 0.f;
            }
        }
        __syncthreads();

        // phase 1: tanh hidden -> fp16 tile in smem
        {
            float4 fv = ((const float4*)ft)[tl];
            char* row = sm + OF_H + tl*STRIDE_H + kh*2;
#pragma unroll 2
            for (int k8 = 0; k8 < 128; k8 += 8) {
                uint32_t ph[4];
#pragma unroll
                for (int j = 0; j < 4; j++) {
                    int k = kh + k8 + j*2;
                    float4 w0 = *(const float4*)(wks + 4*k);
                    float4 w1 = *(const float4*)(wks + 4*(k+1));
                    float z0 = fmaf(fv.x,w0.x, fmaf(fv.y,w0.y, fmaf(fv.z,w0.z, fmaf(fv.w,w0.w, zbs[k]))));
                    float z1 = fmaf(fv.x,w1.x, fmaf(fv.y,w1.y, fmaf(fv.z,w1.z, fmaf(fv.w,w1.w, zbs[k+1]))));
                    ph[j] = packh2(tanh_fast(z0), tanh_fast(z1));
                }
                *(uint4*)(row + k8*2) = make_uint4(ph[0], ph[1], ph[2], ph[3]);
            }
        }
        __syncthreads();

        // phase 2: single-pass fp16 mma
        float acc[6][4];
#pragma unroll
        for (int nt = 0; nt < 6; nt++) {
            acc[nt][0] = 0.f; acc[nt][1] = 0.f; acc[nt][2] = 0.f; acc[nt][3] = 0.f;
        }
#pragma unroll 4
        for (int ks = 0; ks < 16; ks++) {
            uint32_t koff = (uint32_t)ks * 32;
            uint32_t a0, a1, a2, a3;
            LDMATRIX_X4(a0, a1, a2, a3, a_base + koff);
#pragma unroll
            for (int nt = 0; nt < 6; nt++) {
                uint32_t bo = (uint32_t)(nt*8)*STRIDE_H + koff;
                uint32_t b0 = *(const uint32_t*)(b_w + bo);
                uint32_t b1 = *(const uint32_t*)(b_w + bo + 16);
                MMA16816F16(acc[nt], a0, a1, a2, a3, b0, b1);
            }
        }

        // epilogue: bias + activation -> transposed fp16 [s][c][t]
        {
            int t0 = tb + w*16 + (lane >> 2);
            int t1 = t0 + 8;
#pragma unroll
            for (int nt = 0; nt < 6; nt++) {
                int c0 = nt*8 + (lane & 3)*2;
                int grp = c0 >> 4;                // 0 km(exp), 1 ki(relu), 2 ke(exp)
                float v00 = acc[nt][0] + bias0[nt], v01 = acc[nt][1] + bias1[nt];
                float v10 = acc[nt][2] + bias0[nt], v11 = acc[nt][3] + bias1[nt];
                if (grp == 1) {
                    v00 = fmaxf(v00, 0.f); v01 = fmaxf(v01, 0.f);
                    v10 = fmaxf(v10, 0.f); v11 = fmaxf(v11, 0.f);
                } else {
                    v00 = __expf(v00); v01 = __expf(v01);
                    v10 = __expf(v10); v11 = __expf(v11);
                }
                __half* r0 = g_k3 + ((size_t)s*48 + c0)*NT;
                __half* r1 = r0 + NT;
                if (t0 < NT) { r0[t0] = __float2half(v00); r1[t0] = __float2half(v01); }
                if (t1 < NT) { r0[t1] = __float2half(v10); r1[t1] = __float2half(v11); }
            }
        }
        __syncthreads();
    }
}

// ---------------- kernel 4: fused scan, contiguous fp16 t-streams, block-8 vector loads ----------------
__global__ void __launch_bounds__(128) k_scan(float* __restrict__ out) {
    int gid = blockIdx.x * blockDim.x + threadIdx.x;   // = s*NH + h
    int site = gid >> 4, h = gid & 15;
    float kp = g_prm[0][gid], ksg = g_prm[1][gid], kd = g_prm[2][gid];
    float gd = g_prm[3][gid], gl = g_prm[4][gid], qb = g_prm[5][gid];
    float gi = g_prm[6][gid], ge = g_prm[7][gid], ga = g_prm[8][gid];
    const float4* wrp = (const float4*)(g_wr + gid*NR);
    float4 wa = wrp[0], wb = wrp[1];
    float wrv[8] = {wa.x, wa.y, wa.z, wa.w, wb.x, wb.y, wb.z, wb.w};

    float A[8];
#pragma unroll
    for (int j = 0; j < 8; j++) A[j] = 0.f;
    float Sf = 0.f, Ss = 0.f, Sg = 0.f;

    const uint4* pkm = (const uint4*)(g_k3 + ((size_t)site*48 + h)*NT);        // 8 halfs / load
    const uint4* pki = (const uint4*)(g_k3 + ((size_t)site*48 + 16 + h)*NT);
    const uint4* pke = (const uint4*)(g_k3 + ((size_t)site*48 + 32 + h)*NT);
    const float4* pPs = (const float4*)(g_Ps + site*NT);                       // 4 floats / load
    const float4* pPl = (const float4*)(g_Pl + site*NT);
    const float4* pEv = (const float4*)(g_Ev + site*NT);

    // current block buffers
    uint4 ckm = pkm[0], cki = pki[0], cke = pke[0];
    float4 cPs0 = pPs[0], cPs1 = pPs[1];
    float4 cPl0 = pPl[0], cPl1 = pPl[1];
    float4 cEv0 = pEv[0], cEv1 = pEv[1];

    for (int blk = 0; blk < NT/8; blk++) {
        // prefetch next block
        uint4 nkm, nki, nke;
        float4 nPs0, nPs1, nPl0, nPl1, nEv0, nEv1;
        if (blk + 1 < NT/8) {
            nkm = pkm[blk+1]; nki = pki[blk+1]; nke = pke[blk+1];
            nPs0 = pPs[2*blk+2]; nPs1 = pPs[2*blk+3];
            nPl0 = pPl[2*blk+2]; nPl1 = pPl[2*blk+3];
            nEv0 = pEv[2*blk+2]; nEv1 = pEv[2*blk+3];
        }
        int tbase = blk * 8;
#pragma unroll
        for (int i = 0; i < 8; i++) {
            int tc = tbase + i;
            float kmt = geth(ckm, i), kit = geth(cki, i), ket = geth(cke, i);
            float Pst = getf(cPs0, cPs1, i);
            float Plt = getf(cPl0, cPl1, i);
            float Evt = getf(cEv0, cEv1, i);

            Sf += Pst;
            float qf = fminf(Sf, kmt); Sf -= qf;
            float inflow = qf + Plt;
            float qd = inflow * gi;
            Ss += inflow * (1.f - gi);
            float E = fminf(fmaxf(Ss, 0.f), Evt * ket * ge); Ss -= E;
            float qi = fminf(kit, fmaxf(Ss, 0.f)); Ss -= qi;
            float qp = kp * fmaxf(Ss - gl, 0.f);
            float qsa = ksg * fminf(fmaxf(Ss, 0.f), gl);
            Ss -= qp + qsa;
            Sg += qsa * gd;
            float qg = fmaf(kd, Sg, qb); Sg *= (1.f - kd);
            float q = qp + qsa * (1.f - gd) + qg + qd + qi;

#pragma unroll
            for (int j = 0; j < 8; j++) A[j] = fmaf(q, wrv[j], A[j]);

            if (tc >= NR - 1) {
                float v = A[0] * ga;
                v += __shfl_xor_sync(0xffffffffu, v, 1);
                v += __shfl_xor_sync(0xffffffffu, v, 2);
                v += __shfl_xor_sync(0xffffffffu, v, 4);
                v += __shfl_xor_sync(0xffffffffu, v, 8);
                if (h == 0) out[(tc - (NR-1))*NS + site] = v;
            }
#pragma unroll
            for (int j = 0; j < 7; j++) A[j] = A[j+1];
            A[7] = 0.f;
        }
        if (blk + 1 < NT/8) {
            ckm = nkm; cki = nki; cke = nke;
            cPs0 = nPs0; cPs1 = nPs1;
            cPl0 = nPl0; cPl1 = nPl1;
            cEv0 = nEv0; cEv1 = nEv1;
        }
    }
}

// ---------------- launch ----------------
extern "C" void kernel_launch(void* const* d_in, const int* in_sizes, int n_in,
                              void* d_out, int out_size) {
    const float* x      = (const float*)d_in[0];
    const float* xc     = (const float*)d_in[1];
    const float* W_fc   = (const float*)d_in[2];
    const float* b_fc   = (const float*)d_in[3];
    const float* W_r    = (const float*)d_in[4];
    const float* b_r    = (const float*)d_in[5];
    const float* W_g    = (const float*)d_in[6];
    const float* b_g    = (const float*)d_in[7];
    const float* W_kin  = (const float*)d_in[8];
    const float* b_kin  = (const float*)d_in[9];
    const float* W_kout = (const float*)d_in[10];
    const float* b_kout = (const float*)d_in[11];
    float* out = (float*)d_out;

    k_state<<<NS, HS>>>(xc, W_fc, b_fc, b_kin);
    k_params<<<NS, 256>>>(W_r, b_r, W_g, b_g);

    cudaFuncSetAttribute(k_kparam, cudaFuncAttributeMaxDynamicSharedMemorySize, SMEM_BYTES);
    k_kparam<<<NS, 256, SMEM_BYTES>>>(x, W_kin, W_kout, b_kout);

    k_scan<<<(NS*NH)/128, 128>>>(out);
}